// round 6
// baseline (speedup 1.0000x reference)
#include <cuda_runtime.h>
#include <cuda_bf16.h>
#include <math.h>
#include <stdint.h>

// Problem constants (fixed by dataset)
#define NB   32      // batch
#define TMEL 2000    // mel time
#define TPH  513     // phonemes + blank
#define DIM  256     // model dim
#define MELD 80      // mel feature dim
#define SPAD 520     // padded phoneme axis for dots/probs (520 % 8 == 0)

static __device__ float g_wpack   [8 * 768 * 512];        // packed GLU conv weights [blk][768][512]
static __device__ float g_wpack_f [240 * 256];            // packed front conv weights [240][256]
static __device__ float g_bufA    [NB * TMEL * DIM];      // mel ping
static __device__ float g_bufB    [NB * TMEL * DIM];      // mel pong
static __device__ float g_y       [NB * TMEL * 2 * DIM];  // conv output scratch (shared mel/ph)
static __device__ float g_ph0     [NB * TPH * DIM];       // ph ping
static __device__ float g_ph1     [NB * TPH * DIM];       // ph pong
static __device__ float g_dots    [NB * TMEL * SPAD];     // logits -> probs
static __device__ float g_phsq    [NB * TPH];             // ||ph_enc||^2

// ---------------------------------------------------------------------------
// Weight packing
// ---------------------------------------------------------------------------
__global__ void pack_glu_w(const float* __restrict__ w, float* __restrict__ wp) {
    int i = blockIdx.x * blockDim.x + threadIdx.x;
    if (i >= 4 * 768 * 512) return;
    int o   = i & 511;
    int r   = i >> 9;
    int kk  = r % 768;
    int blk = r / 768;
    int tap = kk >> 8;       // kk / 256
    int ci  = kk & 255;
    wp[i] = w[(((size_t)blk * 512 + o) * 256 + ci) * 3 + tap];
}

__global__ void pack_front_w(const float* __restrict__ w, float* __restrict__ wp) {
    int i = blockIdx.x * blockDim.x + threadIdx.x;
    if (i >= 240 * 256) return;
    int o  = i & 255;
    int kk = i >> 8;
    int tap = kk / 80;
    int ci  = kk - tap * 80;
    wp[i] = w[((size_t)o * 80 + ci) * 3 + tap];
}

// ---------------------------------------------------------------------------
// Phoneme embedding (with prepended blank index 0)
// ---------------------------------------------------------------------------
__global__ void embed_kernel(const int* __restrict__ ph, const float* __restrict__ emb,
                             float* __restrict__ out) {
    int row = blockIdx.x;            // b * TPH + s
    int b = row / TPH;
    int s = row - b * TPH;
    int tok = (s == 0) ? 0 : ph[b * 512 + (s - 1)];
    float4 v = *reinterpret_cast<const float4*>(emb + (size_t)tok * 256 + threadIdx.x * 4);
    *reinterpret_cast<float4*>(out + (size_t)row * 256 + threadIdx.x * 4) = v;
}

// ---------------------------------------------------------------------------
// Generic 128x128 fp32 GEMM, 256 threads, 8x8 per thread, double buffered.
// MODE 0: GLU conv GEMM   A = x[B,T,256] (masked, 3-tap), B = wpack[768,512], C = y[B,T,512]
// MODE 1: front conv      A = mels[B,T,80] (3-tap),      B = [240,256],      C = [B,T,256]
// MODE 2: dots NT GEMM    A = out[B,T,512] (cols 0..255), B = Ep[513,256],   C = logits[B,T,520]
// MODE 3: context NN GEMM A = probs[B,T,520],             B = Ep[513,256],   C = out[B,T,512]+256
// ---------------------------------------------------------------------------
template <int MODE>
__launch_bounds__(256, 2)
__global__ void gemm128(const float* __restrict__ A,
                        const float* __restrict__ Bm,
                        const float* __restrict__ extra,   // bias (0/1) or phsq (2)
                        float* __restrict__ Cg,
                        const int* __restrict__ lens,
                        int lenoff, int T)
{
    constexpr int CI  = (MODE == 1) ? 80 : 256;
    constexpr int K   = (MODE == 0) ? 768 : (MODE == 1) ? 240 : (MODE == 2) ? 256 : 520;
    constexpr int LDA = (MODE <= 1) ? CI : (MODE == 2 ? 512 : 520);
    constexpr int NSTEP = K / 8;

    __shared__ float As[2][8][132];
    __shared__ float Bs[2][8][132];

    const int b   = blockIdx.z;
    const int t0  = blockIdx.x * 128;
    const int n0  = blockIdx.y * 128;
    const int tid = threadIdx.x;

    const float* Ab = A + (size_t)b * T * LDA;
    const float* Bb = (MODE >= 2) ? (Bm + (size_t)b * 513 * 256) : Bm;

    int lim = 0x7fffffff;
    if (MODE == 0 && lens) lim = lens[b] + lenoff;

    // A loader: thread -> (row, 4-wide k chunk)
    const int am  = tid >> 1;
    const int ak4 = (tid & 1) * 4;
    // B loader (modes 0,1,3): thread -> (k row, 4-wide n chunk)
    const int bk = tid >> 5;
    const int bn = (tid & 31) * 4;
    // B loader (mode 2, NT): thread -> (n row, 4-wide k chunk)
    const int nb2 = tid >> 1;
    const int bk4 = (tid & 1) * 4;

    auto loadA = [&](int k0, int buf) {
        float4 v = make_float4(0.f, 0.f, 0.f, 0.f);
        if (MODE <= 1) {
            int kk  = k0 + ak4;
            int tap = kk / CI;
            int ci  = kk - tap * CI;
            int t   = t0 + am + tap - 1;
            if (t >= 0 && t < T && t < lim)
                v = *reinterpret_cast<const float4*>(Ab + (size_t)t * CI + ci);
        } else {
            int t = t0 + am;
            if (t < T)
                v = *reinterpret_cast<const float4*>(Ab + (size_t)t * LDA + k0 + ak4);
        }
        As[buf][ak4 + 0][am] = v.x;
        As[buf][ak4 + 1][am] = v.y;
        As[buf][ak4 + 2][am] = v.z;
        As[buf][ak4 + 3][am] = v.w;
    };

    auto loadB = [&](int k0, int buf) {
        if (MODE <= 1) {
            constexpr int LDB = (MODE == 0) ? 512 : 256;
            float4 v = *reinterpret_cast<const float4*>(Bb + (size_t)(k0 + bk) * LDB + n0 + bn);
            *reinterpret_cast<float4*>(&Bs[buf][bk][bn]) = v;
        } else if (MODE == 2) {
            float4 v = make_float4(0.f, 0.f, 0.f, 0.f);
            int s = n0 + nb2;
            if (s < 513)
                v = *reinterpret_cast<const float4*>(Bb + (size_t)s * 256 + k0 + bk4);
            Bs[buf][bk4 + 0][nb2] = v.x;
            Bs[buf][bk4 + 1][nb2] = v.y;
            Bs[buf][bk4 + 2][nb2] = v.z;
            Bs[buf][bk4 + 3][nb2] = v.w;
        } else {
            float4 v = make_float4(0.f, 0.f, 0.f, 0.f);
            int kr = k0 + bk;
            if (kr < 513)
                v = *reinterpret_cast<const float4*>(Bb + (size_t)kr * 256 + n0 + bn);
            *reinterpret_cast<float4*>(&Bs[buf][bk][bn]) = v;
        }
    };

    const int tx = tid & 15;
    const int ty = tid >> 4;

    float acc[8][8];
#pragma unroll
    for (int i = 0; i < 8; i++)
#pragma unroll
        for (int j = 0; j < 8; j++) acc[i][j] = 0.f;

    loadA(0, 0);
    loadB(0, 0);
    __syncthreads();

    for (int s = 0; s < NSTEP; ++s) {
        int buf = s & 1;
        if (s + 1 < NSTEP) {
            loadA((s + 1) * 8, buf ^ 1);
            loadB((s + 1) * 8, buf ^ 1);
        }
#pragma unroll
        for (int k = 0; k < 8; ++k) {
            float4 a0 = *reinterpret_cast<const float4*>(&As[buf][k][ty * 4]);
            float4 a1 = *reinterpret_cast<const float4*>(&As[buf][k][64 + ty * 4]);
            float4 b0 = *reinterpret_cast<const float4*>(&Bs[buf][k][tx * 4]);
            float4 b1 = *reinterpret_cast<const float4*>(&Bs[buf][k][64 + tx * 4]);
            float av[8] = {a0.x, a0.y, a0.z, a0.w, a1.x, a1.y, a1.z, a1.w};
            float bv[8] = {b0.x, b0.y, b0.z, b0.w, b1.x, b1.y, b1.z, b1.w};
#pragma unroll
            for (int i = 0; i < 8; i++)
#pragma unroll
                for (int j = 0; j < 8; j++)
                    acc[i][j] = fmaf(av[i], bv[j], acc[i][j]);
        }
        __syncthreads();
    }

    // Epilogue
#pragma unroll
    for (int i = 0; i < 8; i++) {
        int m = (i < 4) ? (ty * 4 + i) : (64 + ty * 4 + (i - 4));
        int t = t0 + m;
        if (t >= T) continue;
        if (MODE <= 1) {
            constexpr int LDC = (MODE == 0) ? 512 : 256;
            float* crow = Cg + ((size_t)b * T + t) * LDC;
#pragma unroll
            for (int jh = 0; jh < 2; jh++) {
                int c = jh * 64 + tx * 4;
                float4 o;
                o.x = acc[i][jh * 4 + 0] + extra[n0 + c + 0];
                o.y = acc[i][jh * 4 + 1] + extra[n0 + c + 1];
                o.z = acc[i][jh * 4 + 2] + extra[n0 + c + 2];
                o.w = acc[i][jh * 4 + 3] + extra[n0 + c + 3];
                *reinterpret_cast<float4*>(crow + n0 + c) = o;
            }
        } else if (MODE == 2) {
            float* crow = Cg + ((size_t)b * T + t) * SPAD;
            int lim2 = lens[b] + lenoff;  // valid s < lim2
#pragma unroll
            for (int j = 0; j < 8; j++) {
                int s_ = n0 + ((j < 4) ? (tx * 4 + j) : (64 + tx * 4 + (j - 4)));
                if (s_ < 513) {
                    float vv = 2.f * acc[i][j] - extra[(size_t)b * TPH + s_];
                    if (s_ >= lim2) vv = -1e9f;
                    crow[s_] = vv;
                }
            }
        } else {
            float* crow = Cg + ((size_t)b * T + t) * 512 + 256;
#pragma unroll
            for (int jh = 0; jh < 2; jh++) {
                int c = jh * 64 + tx * 4;
                float4 o;
                o.x = acc[i][jh * 4 + 0];
                o.y = acc[i][jh * 4 + 1];
                o.z = acc[i][jh * 4 + 2];
                o.w = acc[i][jh * 4 + 3];
                *reinterpret_cast<float4*>(crow + n0 + c) = o;
            }
        }
    }
}

// ---------------------------------------------------------------------------
// GLU + residual + sqrt(0.5) epilogue (residual uses masked x)
// ---------------------------------------------------------------------------
__global__ void glu_kernel(const float* __restrict__ y, const float* __restrict__ xin,
                           float* __restrict__ out, const int* __restrict__ lens,
                           int lenoff, int T, int ldout)
{
    size_t i = (size_t)blockIdx.x * blockDim.x + threadIdx.x;
    size_t total = (size_t)NB * T * 64;
    if (i >= total) return;
    size_t bt = i >> 6;
    int c = (int)(i & 63) << 2;
    int b = (int)(bt / T);
    int t = (int)(bt - (size_t)b * T);
    float4 a = *reinterpret_cast<const float4*>(y + bt * 512 + c);
    float4 g = *reinterpret_cast<const float4*>(y + bt * 512 + 256 + c);
    float4 x = *reinterpret_cast<const float4*>(xin + bt * 256 + c);
    if (t >= lens[b] + lenoff) { x.x = 0.f; x.y = 0.f; x.z = 0.f; x.w = 0.f; }
    const float SH = 0.70710678118654752440f;
    float4 o;
    o.x = (a.x / (1.f + expf(-g.x)) + x.x) * SH;
    o.y = (a.y / (1.f + expf(-g.y)) + x.y) * SH;
    o.z = (a.z / (1.f + expf(-g.z)) + x.z) * SH;
    o.w = (a.w / (1.f + expf(-g.w)) + x.w) * SH;
    *reinterpret_cast<float4*>(out + ((size_t)b * T + t) * ldout + c) = o;
}

// ---------------------------------------------------------------------------
// ||ph_enc||^2 per row
// ---------------------------------------------------------------------------
__global__ void phsq_kernel(const float* __restrict__ ep, float* __restrict__ sq) {
    int row = blockIdx.x;
    int lane = threadIdx.x;
    const float* r = ep + (size_t)row * 256;
    float s = 0.f;
#pragma unroll
    for (int j = 0; j < 2; j++) {
        float4 v = *reinterpret_cast<const float4*>(r + lane * 4 + j * 128);
        s += v.x * v.x + v.y * v.y + v.z * v.z + v.w * v.w;
    }
#pragma unroll
    for (int o = 16; o; o >>= 1) s += __shfl_xor_sync(0xffffffffu, s, o);
    if (lane == 0) sq[row] = s;
}

// ---------------------------------------------------------------------------
// Row softmax over 513 logits (stride SPAD), zero the pad columns
// ---------------------------------------------------------------------------
__global__ void softmax_kernel(float* __restrict__ dots) {
    size_t row = blockIdx.x;
    float* p = dots + row * SPAD;
    int tid = threadIdx.x;  // 128 threads
    int lane = tid & 31, wid = tid >> 5;
    __shared__ float red[32];

    float v[5];
    float mx = -3.0e38f;
#pragma unroll
    for (int j = 0; j < 5; j++) {
        int idx = tid + j * 128;
        v[j] = (idx < 513) ? p[idx] : -3.0e38f;
        mx = fmaxf(mx, v[j]);
    }
#pragma unroll
    for (int o = 16; o; o >>= 1) mx = fmaxf(mx, __shfl_xor_sync(0xffffffffu, mx, o));
    if (lane == 0) red[wid] = mx;
    __syncthreads();
    if (tid < 32) {
        float m = (tid < 4) ? red[tid] : -3.0e38f;
#pragma unroll
        for (int o = 2; o; o >>= 1) m = fmaxf(m, __shfl_xor_sync(0xffffffffu, m, o));
        if (tid == 0) red[0] = m;
    }
    __syncthreads();
    mx = red[0];
    __syncthreads();

    float s = 0.f;
#pragma unroll
    for (int j = 0; j < 5; j++) {
        int idx = tid + j * 128;
        if (idx < 513) { v[j] = expf(v[j] - mx); s += v[j]; }
    }
#pragma unroll
    for (int o = 16; o; o >>= 1) s += __shfl_xor_sync(0xffffffffu, s, o);
    if (lane == 0) red[wid] = s;
    __syncthreads();
    if (tid < 32) {
        float t2 = (tid < 4) ? red[tid] : 0.f;
#pragma unroll
        for (int o = 2; o; o >>= 1) t2 += __shfl_xor_sync(0xffffffffu, t2, o);
        if (tid == 0) red[0] = t2;
    }
    __syncthreads();
    float inv = 1.f / red[0];
#pragma unroll
    for (int j = 0; j < 5; j++) {
        int idx = tid + j * 128;
        if (idx < 513) p[idx] = v[j] * inv;
    }
    if (tid < SPAD - 513) p[513 + tid] = 0.f;
}

// ---------------------------------------------------------------------------
// Launcher
// ---------------------------------------------------------------------------
extern "C" void kernel_launch(void* const* d_in, const int* in_sizes, int n_in,
                              void* d_out, int out_size)
{
    const float* mels = (const float*)d_in[0];
    const int*   phon = (const int*)  d_in[1];
    const int*   mlen = (const int*)  d_in[2];
    const int*   plen = (const int*)  d_in[3];
    const float* emb  = (const float*)d_in[4];
    const float* mcw  = (const float*)d_in[5];
    const float* mcb  = (const float*)d_in[6];
    const float* phw  = (const float*)d_in[7];
    const float* phb  = (const float*)d_in[8];
    const float* melw = (const float*)d_in[9];
    const float* melb = (const float*)d_in[10];
    float* out = (float*)d_out;

    float *wp, *wpf, *bufA, *bufB, *y, *ph0, *ph1, *dots, *phsq;
    cudaGetSymbolAddress((void**)&wp,   g_wpack);
    cudaGetSymbolAddress((void**)&wpf,  g_wpack_f);
    cudaGetSymbolAddress((void**)&bufA, g_bufA);
    cudaGetSymbolAddress((void**)&bufB, g_bufB);
    cudaGetSymbolAddress((void**)&y,    g_y);
    cudaGetSymbolAddress((void**)&ph0,  g_ph0);
    cudaGetSymbolAddress((void**)&ph1,  g_ph1);
    cudaGetSymbolAddress((void**)&dots, g_dots);
    cudaGetSymbolAddress((void**)&phsq, g_phsq);

    // 1. pack weights (ph blocks -> slots 0..3, mel blocks -> slots 4..7)
    pack_glu_w<<<(4 * 768 * 512 + 255) / 256, 256>>>(phw, wp);
    pack_glu_w<<<(4 * 768 * 512 + 255) / 256, 256>>>(melw, wp + (size_t)4 * 768 * 512);
    pack_front_w<<<(240 * 256 + 255) / 256, 256>>>(mcw, wpf);

    // 2. phoneme embedding
    embed_kernel<<<NB * TPH, 64>>>(phon, emb, ph0);

    // 3. mel front conv -> bufA
    {
        dim3 g((TMEL + 127) / 128, 2, NB);
        gemm128<1><<<g, 256>>>(mels, wpf, mcb, bufA, nullptr, 0, TMEL);
    }

    // 4. phoneme GLU blocks (mask: valid s <= len  =>  lim = len + 1)
    {
        float* pin = ph0; float* pout = ph1;
        dim3 g((TPH + 127) / 128, 4, NB);
        int nglu = (NB * TPH * 64 + 255) / 256;
        for (int i = 0; i < 4; i++) {
            gemm128<0><<<g, 256>>>(pin, wp + (size_t)i * 768 * 512, phb + i * 512,
                                   y, plen, 1, TPH);
            glu_kernel<<<nglu, 256>>>(y, pin, pout, plen, 1, TPH, 256);
            float* tmp = pin; pin = pout; pout = tmp;
        }
        // final ph encoding now in ph0 (4 swaps: 0->1->0->1->0)
    }

    // 5. mel GLU blocks (mask: valid t < len => lim = len)
    {
        float* pin = bufA; float* pout = bufB;
        dim3 g((TMEL + 127) / 128, 4, NB);
        int nglu = (NB * TMEL * 64 + 255) / 256;
        for (int i = 0; i < 4; i++) {
            gemm128<0><<<g, 256>>>(pin, wp + (size_t)(4 + i) * 768 * 512, melb + i * 512,
                                   y, mlen, 0, TMEL);
            if (i < 3) {
                glu_kernel<<<nglu, 256>>>(y, pin, pout, mlen, 0, TMEL, 256);
                float* tmp = pin; pin = pout; pout = tmp;
            } else {
                // final block writes mel_enc directly to out[:, :, 0:256]
                glu_kernel<<<nglu, 256>>>(y, pin, out, mlen, 0, TMEL, 512);
            }
        }
    }

    // 6. phoneme squared norms
    phsq_kernel<<<NB * TPH, 32>>>(ph0, phsq);

    // 7. dots GEMM -> logits (2*dot - ph_sq, masked). A = out cols 0..255 (stride 512)
    {
        dim3 g((TMEL + 127) / 128, (TPH + 127) / 128, NB);
        gemm128<2><<<g, 256>>>(out, ph0, phsq, dots, plen, 1, TMEL);
    }

    // 8. softmax over phoneme axis
    softmax_kernel<<<NB * TMEL, 128>>>(dots);

    // 9. context GEMM -> out[:, :, 256:512]
    {
        dim3 g((TMEL + 127) / 128, 2, NB);
        gemm128<3><<<g, 256>>>(dots, ph0, nullptr, out, nullptr, 0, TMEL);
    }
}

// round 9
// speedup vs baseline: 2.0614x; 2.0614x over previous
#include <cuda_runtime.h>
#include <cuda_bf16.h>
#include <math.h>
#include <stdint.h>

// Problem constants (fixed by dataset)
#define NB   32
#define TMEL 2000
#define TPH  513
#define DIM  256
#define SPAD 520

static __device__ float g_wpack  [8 * 512 * 768];   // GLU conv weights [blk][N=512][K=768], tf32-rounded
static __device__ float g_wpackf [256 * 256];       // front conv weights [N=256][K=256 padded], tf32-rounded
static __device__ float g_bufA   [NB * TMEL * DIM];
static __device__ float g_bufB   [NB * TMEL * DIM];
static __device__ float g_ph0    [NB * TPH * DIM];
static __device__ float g_ph1    [NB * TPH * DIM];
static __device__ float g_dots   [NB * TMEL * SPAD];
static __device__ float g_phsq   [NB * TPH];

// ---------------------------------------------------------------------------
// Helpers
// ---------------------------------------------------------------------------
__device__ __forceinline__ uint32_t smem_u32(const void* p) {
    uint32_t a;
    asm("{ .reg .u64 t; cvta.to.shared.u64 t, %1; cvt.u32.u64 %0, t; }" : "=r"(a) : "l"(p));
    return a;
}
__device__ __forceinline__ float to_tf32(float x) {
    float r; asm("cvt.rna.tf32.f32 %0, %1;" : "=f"(r) : "f"(x)); return r;
}
__device__ __forceinline__ void cp16(uint32_t dst, const void* src, uint32_t nbytes) {
    asm volatile("cp.async.ca.shared.global [%0], [%1], 16, %2;"
                 :: "r"(dst), "l"(src), "r"(nbytes) : "memory");
}
#define CP_COMMIT() asm volatile("cp.async.commit_group;" ::: "memory")
#define CP_WAIT1()  asm volatile("cp.async.wait_group 1;" ::: "memory")
#define CP_WAIT0()  asm volatile("cp.async.wait_group 0;" ::: "memory")

// mma.sync m16n8k8 tf32 (baseline PTX, legal on sm_103 — tensor pipe HMMA)
__device__ __forceinline__ void mma_tf32(float* c, const uint32_t* a, uint32_t b0, uint32_t b1) {
    asm volatile(
        "mma.sync.aligned.m16n8k8.row.col.f32.tf32.tf32.f32 "
        "{%0,%1,%2,%3}, {%4,%5,%6,%7}, {%8,%9}, {%0,%1,%2,%3};"
        : "+f"(c[0]), "+f"(c[1]), "+f"(c[2]), "+f"(c[3])
        : "r"(a[0]), "r"(a[1]), "r"(a[2]), "r"(a[3]), "r"(b0), "r"(b1));
}

// ---------------------------------------------------------------------------
// Weight packing (to [N][K] K-major, tf32-rounded)
// ---------------------------------------------------------------------------
__global__ void pack_glu_w(const float* __restrict__ w, float* __restrict__ wp) {
    int i = blockIdx.x * blockDim.x + threadIdx.x;
    if (i >= 4 * 512 * 768) return;
    int kk = i % 768;
    int r = i / 768;
    int o = r & 511;
    int blk = r >> 9;
    int tap = kk >> 8;
    int ci = kk & 255;
    wp[i] = to_tf32(w[(((size_t)blk * 512 + o) * 256 + ci) * 3 + tap]);
}

__global__ void pack_front_w(const float* __restrict__ w, float* __restrict__ wp) {
    int i = blockIdx.x * blockDim.x + threadIdx.x;
    if (i >= 256 * 256) return;
    int kk = i & 255;
    int o = i >> 8;
    float v = 0.f;
    if (kk < 240) {
        int tap = kk / 80;
        int ci = kk - tap * 80;
        v = to_tf32(w[((size_t)o * 80 + ci) * 3 + tap]);
    }
    wp[i] = v;
}

// ---------------------------------------------------------------------------
// Phoneme embedding (prepended blank 0)
// ---------------------------------------------------------------------------
__global__ void embed_kernel(const int* __restrict__ ph, const float* __restrict__ emb,
                             float* __restrict__ out) {
    int row = blockIdx.x;
    int b = row / TPH;
    int s = row - b * TPH;
    int tok = (s == 0) ? 0 : ph[b * 512 + (s - 1)];
    float4 v = *reinterpret_cast<const float4*>(emb + (size_t)tok * 256 + threadIdx.x * 4);
    *reinterpret_cast<float4*>(out + (size_t)row * 256 + threadIdx.x * 4) = v;
}

// ---------------------------------------------------------------------------
// tf32 mma.sync conv GEMM with fused GLU epilogue.
// CTA tile: 128 rows x 64 cols, TWO slabs:
//   MODE 0: slab0 = a (weight rows n0+loc), slab1 = g (weight rows n0+256+loc).
//           epilogue: out[t][n0+loc] = ((a+ba)*sigmoid(g+bg) + masked_x) * sqrt(0.5)
//   MODE 1: slab0 -> out cols n0+loc, slab1 -> out cols n0+128+loc; epilogue = +bias
// A: im2col 3-tap over x[B,T,CI] with zero masking (t<0, t>=T, t>=lim).
// 8 warps: wm = w&3 (row quad, 32 rows), wn = w>>2 (col half, 32 cols).
// SMEM: As[2][128][36], Bs[2][2][64][36] floats, cp.async double buffered.
// ---------------------------------------------------------------------------
#define LDP 36
template <int MODE>
__launch_bounds__(256, 2)
__global__ void conv_mma(const float* __restrict__ A, const float* __restrict__ Bw,
                         const float* __restrict__ bias, float* __restrict__ out,
                         const int* __restrict__ lens, int lenoff, int T, int ldout)
{
    constexpr int CI = (MODE == 0) ? 256 : 80;
    constexpr int K  = (MODE == 0) ? 768 : 256;
    constexpr int NS = K / 32;
    constexpr int ABUF = 128 * LDP;           // floats per A buffer
    constexpr int BBUF = 2 * 64 * LDP;        // floats per B buffer (2 slabs)
    constexpr int BBASE = 2 * ABUF;

    extern __shared__ float sm[];

    const int tid = threadIdx.x;
    const int b   = blockIdx.z;
    const int t0  = blockIdx.x * 128;
    const int n0  = blockIdx.y * 64;

    const float* Ab = A + (size_t)b * T * CI;
    const int lim = (MODE == 0) ? (lens[b] + lenoff) : 0x7fffffff;

    // loader mapping
    const int lrow = tid >> 1;
    const int lcb  = (tid & 1) * 16;
    const int slab = lrow >> 6;
    const int nloc = lrow & 63;
    const int wrow = (MODE == 0) ? (n0 + slab * 256 + nloc) : (n0 + slab * 128 + nloc);
    const float* Brow = Bw + (size_t)wrow * K;

    const uint32_t smb = smem_u32(sm);

    auto loadStage = [&](int s) {
        const int buf = s & 1;
        const int k0 = s * 32;
        // A
        uint32_t adst = smb + (buf * ABUF + lrow * LDP + lcb) * 4;
#pragma unroll
        for (int j = 0; j < 4; j++) {
            int kk = k0 + lcb + j * 4;
            int tap = kk / CI;
            int ci = kk - tap * CI;
            int t = t0 + lrow + tap - 1;
            bool ok = (t >= 0) && (t < T) && (t < lim);
            if (MODE == 1) ok = ok && (kk < 240);
            int tc = ok ? t : 0;
            cp16(adst + j * 16, Ab + (size_t)tc * CI + ci, ok ? 16u : 0u);
        }
        // B
        uint32_t bdst = smb + (BBASE + buf * BBUF + slab * (64 * LDP) + nloc * LDP + lcb) * 4;
        const float* bsrc = Brow + k0 + lcb;
#pragma unroll
        for (int j = 0; j < 4; j++)
            cp16(bdst + j * 16, bsrc + j * 4, 16u);
        CP_COMMIT();
    };

    // mma thread mapping
    const int lane = tid & 31;
    const int g    = lane >> 2;
    const int tIg  = lane & 3;
    const int wm   = (tid >> 5) & 3;
    const int wn   = (tid >> 5) >> 2;

    float acc[2][2][4][4];
#pragma unroll
    for (int s1 = 0; s1 < 2; s1++)
#pragma unroll
        for (int mt = 0; mt < 2; mt++)
#pragma unroll
            for (int nt = 0; nt < 4; nt++)
#pragma unroll
                for (int q = 0; q < 4; q++) acc[s1][mt][nt][q] = 0.f;

    loadStage(0);

    for (int s = 0; s < NS; ++s) {
        const int buf = s & 1;
        if (s + 1 < NS) { loadStage(s + 1); CP_WAIT1(); }
        else            { CP_WAIT0(); }
        __syncthreads();

        const float* As = sm + buf * ABUF;
        const float* Bs = sm + BBASE + buf * BBUF;
#pragma unroll
        for (int ks = 0; ks < 4; ks++) {
            const int kb = ks * 8 + tIg;
            uint32_t af[2][4];
#pragma unroll
            for (int mt = 0; mt < 2; mt++) {
                const float* ar = As + (wm * 32 + mt * 16 + g) * LDP;
                af[mt][0] = __float_as_uint(ar[kb]);
                af[mt][1] = __float_as_uint(ar[8 * LDP + kb]);
                af[mt][2] = __float_as_uint(ar[kb + 4]);
                af[mt][3] = __float_as_uint(ar[8 * LDP + kb + 4]);
            }
#pragma unroll
            for (int s1 = 0; s1 < 2; s1++) {
#pragma unroll
                for (int nt = 0; nt < 4; nt++) {
                    const float* br = Bs + s1 * (64 * LDP) + (wn * 32 + nt * 8 + g) * LDP;
                    uint32_t b0 = __float_as_uint(br[kb]);
                    uint32_t b1 = __float_as_uint(br[kb + 4]);
                    mma_tf32(acc[s1][0][nt], af[0], b0, b1);
                    mma_tf32(acc[s1][1][nt], af[1], b0, b1);
                }
            }
        }
        __syncthreads();
    }

    // Epilogue
    const float SH = 0.70710678118654752440f;
#pragma unroll
    for (int mt = 0; mt < 2; mt++) {
#pragma unroll
        for (int h = 0; h < 2; h++) {
            const int t = t0 + wm * 32 + mt * 16 + g + 8 * h;
            if (t >= T) continue;
            if (MODE == 0) {
                const bool xon = (t < lim);
                const float* xr = Ab + (size_t)t * 256;
                float* orow = out + ((size_t)b * T + t) * ldout;
#pragma unroll
                for (int nt = 0; nt < 4; nt++) {
                    const int c = n0 + wn * 32 + nt * 8 + 2 * tIg;
                    float a0 = acc[0][mt][nt][2 * h + 0] + __ldg(bias + c + 0);
                    float a1 = acc[0][mt][nt][2 * h + 1] + __ldg(bias + c + 1);
                    float g0 = acc[1][mt][nt][2 * h + 0] + __ldg(bias + 256 + c + 0);
                    float g1 = acc[1][mt][nt][2 * h + 1] + __ldg(bias + 256 + c + 1);
                    float2 x = make_float2(0.f, 0.f);
                    if (xon) x = *reinterpret_cast<const float2*>(xr + c);
                    float2 o;
                    o.x = (a0 / (1.f + expf(-g0)) + x.x) * SH;
                    o.y = (a1 / (1.f + expf(-g1)) + x.y) * SH;
                    *reinterpret_cast<float2*>(orow + c) = o;
                }
            } else {
                float* orow = out + ((size_t)b * T + t) * ldout;
#pragma unroll
                for (int s1 = 0; s1 < 2; s1++) {
#pragma unroll
                    for (int nt = 0; nt < 4; nt++) {
                        const int c = n0 + s1 * 128 + wn * 32 + nt * 8 + 2 * tIg;
                        float2 o;
                        o.x = acc[s1][mt][nt][2 * h + 0] + __ldg(bias + c + 0);
                        o.y = acc[s1][mt][nt][2 * h + 1] + __ldg(bias + c + 1);
                        *reinterpret_cast<float2*>(orow + c) = o;
                    }
                }
            }
        }
    }
}

// ---------------------------------------------------------------------------
// fp32 SGEMM (attention: MODE 2 = dots NT, MODE 3 = context NN) — proven path
// ---------------------------------------------------------------------------
template <int MODE>
__launch_bounds__(256, 2)
__global__ void gemm128(const float* __restrict__ A,
                        const float* __restrict__ Bm,
                        const float* __restrict__ extra,
                        float* __restrict__ Cg,
                        const int* __restrict__ lens,
                        int lenoff, int T)
{
    constexpr int K   = (MODE == 2) ? 256 : 520;
    constexpr int LDA = (MODE == 2) ? 512 : 520;
    constexpr int NSTEP = K / 8;

    __shared__ float As[2][8][132];
    __shared__ float Bs[2][8][132];

    const int b   = blockIdx.z;
    const int t0  = blockIdx.x * 128;
    const int n0  = blockIdx.y * 128;
    const int tid = threadIdx.x;

    const float* Ab = A + (size_t)b * T * LDA;
    const float* Bb = Bm + (size_t)b * 513 * 256;

    const int am  = tid >> 1;
    const int ak4 = (tid & 1) * 4;
    const int bk  = tid >> 5;
    const int bn  = (tid & 31) * 4;
    const int nb2 = tid >> 1;
    const int bk4 = (tid & 1) * 4;

    auto loadA = [&](int k0, int buf) {
        float4 v = make_float4(0.f, 0.f, 0.f, 0.f);
        int t = t0 + am;
        if (t < T)
            v = *reinterpret_cast<const float4*>(Ab + (size_t)t * LDA + k0 + ak4);
        As[buf][ak4 + 0][am] = v.x;
        As[buf][ak4 + 1][am] = v.y;
        As[buf][ak4 + 2][am] = v.z;
        As[buf][ak4 + 3][am] = v.w;
    };

    auto loadB = [&](int k0, int buf) {
        if (MODE == 2) {
            float4 v = make_float4(0.f, 0.f, 0.f, 0.f);
            int s = n0 + nb2;
            if (s < 513)
                v = *reinterpret_cast<const float4*>(Bb + (size_t)s * 256 + k0 + bk4);
            Bs[buf][bk4 + 0][nb2] = v.x;
            Bs[buf][bk4 + 1][nb2] = v.y;
            Bs[buf][bk4 + 2][nb2] = v.z;
            Bs[buf][bk4 + 3][nb2] = v.w;
        } else {
            float4 v = make_float4(0.f, 0.f, 0.f, 0.f);
            int kr = k0 + bk;
            if (kr < 513)
                v = *reinterpret_cast<const float4*>(Bb + (size_t)kr * 256 + n0 + bn);
            *reinterpret_cast<float4*>(&Bs[buf][bk][bn]) = v;
        }
    };

    const int tx = tid & 15;
    const int ty = tid >> 4;

    float acc[8][8];
#pragma unroll
    for (int i = 0; i < 8; i++)
#pragma unroll
        for (int j = 0; j < 8; j++) acc[i][j] = 0.f;

    loadA(0, 0);
    loadB(0, 0);
    __syncthreads();

    for (int s = 0; s < NSTEP; ++s) {
        int buf = s & 1;
        if (s + 1 < NSTEP) {
            loadA((s + 1) * 8, buf ^ 1);
            loadB((s + 1) * 8, buf ^ 1);
        }
#pragma unroll
        for (int k = 0; k < 8; ++k) {
            float4 a0 = *reinterpret_cast<const float4*>(&As[buf][k][ty * 4]);
            float4 a1 = *reinterpret_cast<const float4*>(&As[buf][k][64 + ty * 4]);
            float4 b0 = *reinterpret_cast<const float4*>(&Bs[buf][k][tx * 4]);
            float4 b1 = *reinterpret_cast<const float4*>(&Bs[buf][k][64 + tx * 4]);
            float av[8] = {a0.x, a0.y, a0.z, a0.w, a1.x, a1.y, a1.z, a1.w};
            float bv[8] = {b0.x, b0.y, b0.z, b0.w, b1.x, b1.y, b1.z, b1.w};
#pragma unroll
            for (int i = 0; i < 8; i++)
#pragma unroll
                for (int j = 0; j < 8; j++)
                    acc[i][j] = fmaf(av[i], bv[j], acc[i][j]);
        }
        __syncthreads();
    }

#pragma unroll
    for (int i = 0; i < 8; i++) {
        int m = (i < 4) ? (ty * 4 + i) : (64 + ty * 4 + (i - 4));
        int t = t0 + m;
        if (t >= T) continue;
        if (MODE == 2) {
            float* crow = Cg + ((size_t)b * T + t) * SPAD;
            int lim2 = lens[b] + lenoff;
#pragma unroll
            for (int j = 0; j < 8; j++) {
                int s_ = n0 + ((j < 4) ? (tx * 4 + j) : (64 + tx * 4 + (j - 4)));
                if (s_ < 513) {
                    float vv = 2.f * acc[i][j] - extra[(size_t)b * TPH + s_];
                    if (s_ >= lim2) vv = -1e9f;
                    crow[s_] = vv;
                }
            }
        } else {
            float* crow = Cg + ((size_t)b * T + t) * 512 + 256;
#pragma unroll
            for (int jh = 0; jh < 2; jh++) {
                int c = jh * 64 + tx * 4;
                float4 o;
                o.x = acc[i][jh * 4 + 0];
                o.y = acc[i][jh * 4 + 1];
                o.z = acc[i][jh * 4 + 2];
                o.w = acc[i][jh * 4 + 3];
                *reinterpret_cast<float4*>(crow + n0 + c) = o;
            }
        }
    }
}

// ---------------------------------------------------------------------------
// ||ph_enc||^2 per row
// ---------------------------------------------------------------------------
__global__ void phsq_kernel(const float* __restrict__ ep, float* __restrict__ sq) {
    int row = blockIdx.x;
    int lane = threadIdx.x;
    const float* r = ep + (size_t)row * 256;
    float s = 0.f;
#pragma unroll
    for (int j = 0; j < 2; j++) {
        float4 v = *reinterpret_cast<const float4*>(r + lane * 4 + j * 128);
        s += v.x * v.x + v.y * v.y + v.z * v.z + v.w * v.w;
    }
#pragma unroll
    for (int o = 16; o; o >>= 1) s += __shfl_xor_sync(0xffffffffu, s, o);
    if (lane == 0) sq[row] = s;
}

// ---------------------------------------------------------------------------
// Row softmax over 513 logits (stride SPAD), zero pad columns
// ---------------------------------------------------------------------------
__global__ void softmax_kernel(float* __restrict__ dots) {
    size_t row = blockIdx.x;
    float* p = dots + row * SPAD;
    int tid = threadIdx.x;
    int lane = tid & 31, wid = tid >> 5;
    __shared__ float red[32];

    float v[5];
    float mx = -3.0e38f;
#pragma unroll
    for (int j = 0; j < 5; j++) {
        int idx = tid + j * 128;
        v[j] = (idx < 513) ? p[idx] : -3.0e38f;
        mx = fmaxf(mx, v[j]);
    }
#pragma unroll
    for (int o = 16; o; o >>= 1) mx = fmaxf(mx, __shfl_xor_sync(0xffffffffu, mx, o));
    if (lane == 0) red[wid] = mx;
    __syncthreads();
    if (tid < 32) {
        float m = (tid < 4) ? red[tid] : -3.0e38f;
#pragma unroll
        for (int o = 2; o; o >>= 1) m = fmaxf(m, __shfl_xor_sync(0xffffffffu, m, o));
        if (tid == 0) red[0] = m;
    }
    __syncthreads();
    mx = red[0];
    __syncthreads();

    float s = 0.f;
#pragma unroll
    for (int j = 0; j < 5; j++) {
        int idx = tid + j * 128;
        if (idx < 513) { v[j] = expf(v[j] - mx); s += v[j]; }
    }
#pragma unroll
    for (int o = 16; o; o >>= 1) s += __shfl_xor_sync(0xffffffffu, s, o);
    if (lane == 0) red[wid] = s;
    __syncthreads();
    if (tid < 32) {
        float t2 = (tid < 4) ? red[tid] : 0.f;
#pragma unroll
        for (int o = 2; o; o >>= 1) t2 += __shfl_xor_sync(0xffffffffu, t2, o);
        if (tid == 0) red[0] = t2;
    }
    __syncthreads();
    float inv = 1.f / red[0];
#pragma unroll
    for (int j = 0; j < 5; j++) {
        int idx = tid + j * 128;
        if (idx < 513) p[idx] = v[j] * inv;
    }
    if (tid < SPAD - 513) p[513 + tid] = 0.f;
}

// ---------------------------------------------------------------------------
// Launcher
// ---------------------------------------------------------------------------
extern "C" void kernel_launch(void* const* d_in, const int* in_sizes, int n_in,
                              void* d_out, int out_size)
{
    const float* mels = (const float*)d_in[0];
    const int*   phon = (const int*)  d_in[1];
    const int*   mlen = (const int*)  d_in[2];
    const int*   plen = (const int*)  d_in[3];
    const float* emb  = (const float*)d_in[4];
    const float* mcw  = (const float*)d_in[5];
    const float* mcb  = (const float*)d_in[6];
    const float* phw  = (const float*)d_in[7];
    const float* phb  = (const float*)d_in[8];
    const float* melw = (const float*)d_in[9];
    const float* melb = (const float*)d_in[10];
    float* out = (float*)d_out;

    float *wp, *wpf, *bufA, *bufB, *ph0, *ph1, *dots, *phsq;
    cudaGetSymbolAddress((void**)&wp,   g_wpack);
    cudaGetSymbolAddress((void**)&wpf,  g_wpackf);
    cudaGetSymbolAddress((void**)&bufA, g_bufA);
    cudaGetSymbolAddress((void**)&bufB, g_bufB);
    cudaGetSymbolAddress((void**)&ph0,  g_ph0);
    cudaGetSymbolAddress((void**)&ph1,  g_ph1);
    cudaGetSymbolAddress((void**)&dots, g_dots);
    cudaGetSymbolAddress((void**)&phsq, g_phsq);

    // SMEM: (2*128*36 + 2*2*64*36) floats = 18432 floats = 73728 bytes
    const int SMEMSZ = (2 * 128 * LDP + 2 * 2 * 64 * LDP) * 4;
    cudaFuncSetAttribute(conv_mma<0>, cudaFuncAttributeMaxDynamicSharedMemorySize, SMEMSZ);
    cudaFuncSetAttribute(conv_mma<1>, cudaFuncAttributeMaxDynamicSharedMemorySize, SMEMSZ);

    // 1. pack weights (ph -> slots 0..3, mel -> slots 4..7)
    pack_glu_w<<<(4 * 512 * 768 + 255) / 256, 256>>>(phw, wp);
    pack_glu_w<<<(4 * 512 * 768 + 255) / 256, 256>>>(melw, wp + (size_t)4 * 512 * 768);
    pack_front_w<<<(256 * 256 + 255) / 256, 256>>>(mcw, wpf);

    // 2. phoneme embedding
    embed_kernel<<<NB * TPH, 64>>>(phon, emb, ph0);

    // 3. mel front conv -> bufA (tf32 tensor, plain bias epilogue)
    {
        dim3 g((TMEL + 127) / 128, 2, NB);
        conv_mma<1><<<g, 256, SMEMSZ>>>(mels, wpf, mcb, bufA, nullptr, 0, TMEL, 256);
    }

    // 4. phoneme GLU blocks (valid s <= len => lim = len + 1)
    {
        float* pin = ph0; float* pout = ph1;
        dim3 g((TPH + 127) / 128, 4, NB);
        for (int i = 0; i < 4; i++) {
            conv_mma<0><<<g, 256, SMEMSZ>>>(pin, wp + (size_t)i * 512 * 768, phb + i * 512,
                                            pout, plen, 1, TPH, 256);
            float* tmp = pin; pin = pout; pout = tmp;
        }
        // final ph encoding in ph0
    }

    // 5. mel GLU blocks (valid t < len => lim = len)
    {
        float* pin = bufA; float* pout = bufB;
        dim3 g((TMEL + 127) / 128, 4, NB);
        for (int i = 0; i < 4; i++) {
            if (i < 3) {
                conv_mma<0><<<g, 256, SMEMSZ>>>(pin, wp + (size_t)(4 + i) * 512 * 768,
                                                melb + i * 512, pout, mlen, 0, TMEL, 256);
                float* tmp = pin; pin = pout; pout = tmp;
            } else {
                // final block writes mel_enc directly into out[:, :, 0:256]
                conv_mma<0><<<g, 256, SMEMSZ>>>(pin, wp + (size_t)(4 + i) * 512 * 768,
                                                melb + i * 512, out, mlen, 0, TMEL, 512);
            }
        }
    }

    // 6. phoneme squared norms
    phsq_kernel<<<NB * TPH, 32>>>(ph0, phsq);

    // 7. dots (fp32): logits = 2*dot - ph_sq, masked
    {
        dim3 g((TMEL + 127) / 128, (TPH + 127) / 128, NB);
        gemm128<2><<<g, 256>>>(out, ph0, phsq, dots, plen, 1, TMEL);
    }

    // 8. softmax over phoneme axis
    softmax_kernel<<<NB * TMEL, 128>>>(dots);

    // 9. context (fp32) -> out[:, :, 256:512]
    {
        dim3 g((TMEL + 127) / 128, 2, NB);
        gemm128<3><<<g, 256>>>(dots, ph0, nullptr, out, nullptr, 0, TMEL);
    }
}

// round 11
// speedup vs baseline: 2.8507x; 1.3829x over previous
#include <cuda_runtime.h>
#include <cuda_fp16.h>
#include <cuda_bf16.h>
#include <math.h>
#include <stdint.h>

// Problem constants (fixed by dataset)
#define NB   32
#define TMEL 2000
#define TPH  513
#define DIM  256
#define SPAD 520

// fp32 buffers
static __device__ float g_bufA [NB * TMEL * DIM];
static __device__ float g_bufB [NB * TMEL * DIM];
static __device__ float g_ph0  [NB * TPH * DIM];
static __device__ float g_ph1  [NB * TPH * DIM];
static __device__ float g_dots [NB * TMEL * SPAD];
static __device__ float g_phsq [NB * TPH];
// fp16 weights + activation shadows
static __device__ __half g_hw   [8 * 512 * 768];   // GLU weights [blk][N=512][K=768]
static __device__ __half g_hwf  [256 * 256];       // front conv [N=256][K pad 256]
static __device__ __half g_hmels[NB * TMEL * 80];
static __device__ __half g_hA   [NB * TMEL * DIM];
static __device__ __half g_hB   [NB * TMEL * DIM];
static __device__ __half g_hp0  [NB * TPH * DIM];
static __device__ __half g_hp1  [NB * TPH * DIM];

// ---------------------------------------------------------------------------
// Helpers
// ---------------------------------------------------------------------------
__device__ __forceinline__ uint32_t smem_u32(const void* p) {
    uint32_t a;
    asm("{ .reg .u64 t; cvta.to.shared.u64 t, %1; cvt.u32.u64 %0, t; }" : "=r"(a) : "l"(p));
    return a;
}
__device__ __forceinline__ void cp16(uint32_t dst, const void* src, uint32_t nbytes) {
    asm volatile("cp.async.ca.shared.global [%0], [%1], 16, %2;"
                 :: "r"(dst), "l"(src), "r"(nbytes) : "memory");
}
#define CP_COMMIT() asm volatile("cp.async.commit_group;" ::: "memory")
#define CP_WAIT1()  asm volatile("cp.async.wait_group 1;" ::: "memory")
#define CP_WAIT0()  asm volatile("cp.async.wait_group 0;" ::: "memory")

// mma.sync m16n8k16 fp16 inputs, fp32 accumulate (baseline PTX, sm_80+)
__device__ __forceinline__ void mma_f16(float* c, const uint32_t* a, uint32_t b0, uint32_t b1) {
    asm volatile(
        "mma.sync.aligned.m16n8k16.row.col.f32.f16.f16.f32 "
        "{%0,%1,%2,%3}, {%4,%5,%6,%7}, {%8,%9}, {%0,%1,%2,%3};"
        : "+f"(c[0]), "+f"(c[1]), "+f"(c[2]), "+f"(c[3])
        : "r"(a[0]), "r"(a[1]), "r"(a[2]), "r"(a[3]), "r"(b0), "r"(b1));
}

// ---------------------------------------------------------------------------
// Weight packing (to [N][K] K-major, fp16 round-to-nearest)
// ---------------------------------------------------------------------------
__global__ void pack_glu_w(const float* __restrict__ w, __half* __restrict__ wp) {
    int i = blockIdx.x * blockDim.x + threadIdx.x;
    if (i >= 4 * 512 * 768) return;
    int kk = i % 768;
    int r = i / 768;
    int o = r & 511;
    int blk = r >> 9;
    int tap = kk >> 8;
    int ci = kk & 255;
    wp[i] = __float2half_rn(w[(((size_t)blk * 512 + o) * 256 + ci) * 3 + tap]);
}

__global__ void pack_front_w(const float* __restrict__ w, __half* __restrict__ wp) {
    int i = blockIdx.x * blockDim.x + threadIdx.x;
    if (i >= 256 * 256) return;
    int kk = i & 255;
    int o = i >> 8;
    float v = 0.f;
    if (kk < 240) {
        int tap = kk / 80;
        int ci = kk - tap * 80;
        v = w[((size_t)o * 80 + ci) * 3 + tap];
    }
    wp[i] = __float2half_rn(v);
}

// fp32 -> fp16 convert (mels)
__global__ void f2h_kernel(const float* __restrict__ in, __half* __restrict__ out, int n4) {
    int i = blockIdx.x * blockDim.x + threadIdx.x;
    if (i >= n4) return;
    float4 v = *reinterpret_cast<const float4*>(in + i * 4);
    __half2 h0 = __floats2half2_rn(v.x, v.y);
    __half2 h1 = __floats2half2_rn(v.z, v.w);
    *reinterpret_cast<__half2*>(out + i * 4)     = h0;
    *reinterpret_cast<__half2*>(out + i * 4 + 2) = h1;
}

// ---------------------------------------------------------------------------
// Phoneme embedding (prepended blank 0) -> fp32 + fp16 shadow
// ---------------------------------------------------------------------------
__global__ void embed_kernel(const int* __restrict__ ph, const float* __restrict__ emb,
                             float* __restrict__ out, __half* __restrict__ hout) {
    int row = blockIdx.x;
    int b = row / TPH;
    int s = row - b * TPH;
    int tok = (s == 0) ? 0 : ph[b * 512 + (s - 1)];
    float4 v = *reinterpret_cast<const float4*>(emb + (size_t)tok * 256 + threadIdx.x * 4);
    *reinterpret_cast<float4*>(out + (size_t)row * 256 + threadIdx.x * 4) = v;
    __half2 h0 = __floats2half2_rn(v.x, v.y);
    __half2 h1 = __floats2half2_rn(v.z, v.w);
    *reinterpret_cast<__half2*>(hout + (size_t)row * 256 + threadIdx.x * 4)     = h0;
    *reinterpret_cast<__half2*>(hout + (size_t)row * 256 + threadIdx.x * 4 + 2) = h1;
}

// ---------------------------------------------------------------------------
// fp16 mma.sync conv GEMM with fused GLU epilogue, 3-stage cp.async ring.
// CTA tile: 128 rows x 64 cols, TWO weight slabs:
//   MODE 0: slab0 = a (rows n0+loc), slab1 = g (rows n0+256+loc)
//           out = ((a+ba)*sigmoid(g+bg) + masked_x_fp32) * sqrt(0.5)  [+fp16 shadow]
//   MODE 1: slab0 -> cols n0+loc, slab1 -> cols n0+128+loc; epilogue = +bias [+shadow]
// A: fp16 shadow of x, im2col 3-tap, zero-masked via cp.async src-size=0.
// 8 warps: wm = w&3 (32-row quad), wn = w>>2 (32-col half).
// SMEM halves: per stage A[128][40] + B[128][40]; 3 stages.
// ---------------------------------------------------------------------------
#define LDH 40
template <int MODE>
__launch_bounds__(256, 2)
__global__ void conv_mma(const __half* __restrict__ Ah, const float* __restrict__ Af,
                         const __half* __restrict__ Bw, const float* __restrict__ bias,
                         float* __restrict__ out, __half* __restrict__ hout,
                         const int* __restrict__ lens, int lenoff, int T, int ldout)
{
    constexpr int CI = (MODE == 0) ? 256 : 80;
    constexpr int K  = (MODE == 0) ? 768 : 256;
    constexpr int NS = K / 32;
    constexpr int STAGE = 2 * 128 * LDH;      // halves per stage (A + B)
    constexpr int BOFF  = 128 * LDH;          // B offset within stage

    extern __shared__ __half smh[];

    const int tid = threadIdx.x;
    const int b   = blockIdx.z;
    const int t0  = blockIdx.x * 128;
    const int n0  = blockIdx.y * 64;

    const __half* Ahb = Ah + (size_t)b * T * CI;
    const float*  Afb = Af + (size_t)b * T * 256;
    const int lim = (MODE == 0) ? (lens[b] + lenoff) : 0x7fffffff;

    // loader mapping: row = tid>>1 (0..127), half-chunk offset 0/16
    const int lrow = tid >> 1;
    const int lhc  = (tid & 1) * 16;
    const int slab = lrow >> 6;
    const int nloc = lrow & 63;
    const int wrow = (MODE == 0) ? (n0 + slab * 256 + nloc) : (n0 + slab * 128 + nloc);
    const __half* Brow = Bw + (size_t)wrow * K;

    const uint32_t smb = smem_u32(smh);

    auto loadStage = [&](int s) {
        const int st = s % 3;
        const int k0 = s * 32;
        uint32_t adst = smb + (st * STAGE + lrow * LDH + lhc) * 2;
#pragma unroll
        for (int j = 0; j < 2; j++) {
            int kk = k0 + lhc + j * 8;
            int tap = kk / CI;
            int ci = kk - tap * CI;
            int t = t0 + lrow + tap - 1;
            bool ok = (t >= 0) && (t < T) && (t < lim);
            if (MODE == 1) ok = ok && (kk < 240);
            int tc = ok ? t : 0;
            cp16(adst + j * 16, Ahb + (size_t)tc * CI + ci, ok ? 16u : 0u);
        }
        uint32_t bdst = smb + (st * STAGE + BOFF + lrow * LDH + lhc) * 2;
        const __half* bsrc = Brow + k0 + lhc;
#pragma unroll
        for (int j = 0; j < 2; j++)
            cp16(bdst + j * 16, bsrc + j * 8, 16u);
        CP_COMMIT();
    };

    // mma thread mapping
    const int lane = tid & 31;
    const int g    = lane >> 2;
    const int tIg  = lane & 3;
    const int wm   = (tid >> 5) & 3;
    const int wn   = (tid >> 5) >> 2;

    float acc[2][2][4][4];
#pragma unroll
    for (int s1 = 0; s1 < 2; s1++)
#pragma unroll
        for (int mt = 0; mt < 2; mt++)
#pragma unroll
            for (int nt = 0; nt < 4; nt++)
#pragma unroll
                for (int q = 0; q < 4; q++) acc[s1][mt][nt][q] = 0.f;

    loadStage(0);
    loadStage(1);

    for (int s = 0; s < NS; ++s) {
        if (s + 1 < NS) { CP_WAIT1(); } else { CP_WAIT0(); }
        __syncthreads();
        if (s + 2 < NS) loadStage(s + 2);

        const int st = s % 3;
        const __half* As = smh + st * STAGE;
        const __half* Bs = smh + st * STAGE + BOFF;
#pragma unroll
        for (int ks = 0; ks < 2; ks++) {
            const int kb = ks * 16 + 2 * tIg;
            uint32_t af[2][4];
#pragma unroll
            for (int mt = 0; mt < 2; mt++) {
                const __half* ar = As + (wm * 32 + mt * 16 + g) * LDH;
                af[mt][0] = *reinterpret_cast<const uint32_t*>(ar + kb);
                af[mt][1] = *reinterpret_cast<const uint32_t*>(ar + 8 * LDH + kb);
                af[mt][2] = *reinterpret_cast<const uint32_t*>(ar + kb + 8);
                af[mt][3] = *reinterpret_cast<const uint32_t*>(ar + 8 * LDH + kb + 8);
            }
#pragma unroll
            for (int s1 = 0; s1 < 2; s1++) {
#pragma unroll
                for (int nt = 0; nt < 4; nt++) {
                    const __half* br = Bs + (s1 * 64 + wn * 32 + nt * 8 + g) * LDH;
                    uint32_t b0 = *reinterpret_cast<const uint32_t*>(br + kb);
                    uint32_t b1 = *reinterpret_cast<const uint32_t*>(br + kb + 8);
                    mma_f16(acc[s1][0][nt], af[0], b0, b1);
                    mma_f16(acc[s1][1][nt], af[1], b0, b1);
                }
            }
        }
    }

    // Epilogue (no smem use -> no final barrier needed)
    const float SH = 0.70710678118654752440f;
#pragma unroll
    for (int mt = 0; mt < 2; mt++) {
#pragma unroll
        for (int h = 0; h < 2; h++) {
            const int t = t0 + wm * 32 + mt * 16 + g + 8 * h;
            if (t >= T) continue;
            if (MODE == 0) {
                const bool xon = (t < lim);
                const float* xr = Afb + (size_t)t * 256;
                float*  orow = out  + ((size_t)b * T + t) * ldout;
                __half* hrow = hout + ((size_t)b * T + t) * 256;
#pragma unroll
                for (int nt = 0; nt < 4; nt++) {
                    const int c = n0 + wn * 32 + nt * 8 + 2 * tIg;
                    float a0 = acc[0][mt][nt][2 * h + 0] + __ldg(bias + c + 0);
                    float a1 = acc[0][mt][nt][2 * h + 1] + __ldg(bias + c + 1);
                    float g0 = acc[1][mt][nt][2 * h + 0] + __ldg(bias + 256 + c + 0);
                    float g1 = acc[1][mt][nt][2 * h + 1] + __ldg(bias + 256 + c + 1);
                    float2 x = make_float2(0.f, 0.f);
                    if (xon) x = *reinterpret_cast<const float2*>(xr + c);
                    float2 o;
                    o.x = (a0 / (1.f + expf(-g0)) + x.x) * SH;
                    o.y = (a1 / (1.f + expf(-g1)) + x.y) * SH;
                    *reinterpret_cast<float2*>(orow + c) = o;
                    *reinterpret_cast<__half2*>(hrow + c) = __floats2half2_rn(o.x, o.y);
                }
            } else {
                float*  orow = out  + ((size_t)b * T + t) * ldout;
                __half* hrow = hout + ((size_t)b * T + t) * 256;
#pragma unroll
                for (int s1 = 0; s1 < 2; s1++) {
#pragma unroll
                    for (int nt = 0; nt < 4; nt++) {
                        const int c = n0 + s1 * 128 + wn * 32 + nt * 8 + 2 * tIg;
                        float2 o;
                        o.x = acc[s1][mt][nt][2 * h + 0] + __ldg(bias + c + 0);
                        o.y = acc[s1][mt][nt][2 * h + 1] + __ldg(bias + c + 1);
                        *reinterpret_cast<float2*>(orow + c) = o;
                        *reinterpret_cast<__half2*>(hrow + c) = __floats2half2_rn(o.x, o.y);
                    }
                }
            }
        }
    }
}

// ---------------------------------------------------------------------------
// fp32 SGEMM (attention: MODE 2 = dots NT, MODE 3 = context NN) — proven path
// ---------------------------------------------------------------------------
template <int MODE>
__launch_bounds__(256, 2)
__global__ void gemm128(const float* __restrict__ A,
                        const float* __restrict__ Bm,
                        const float* __restrict__ extra,
                        float* __restrict__ Cg,
                        const int* __restrict__ lens,
                        int lenoff, int T)
{
    constexpr int K   = (MODE == 2) ? 256 : 520;
    constexpr int LDA = (MODE == 2) ? 512 : 520;
    constexpr int NSTEP = K / 8;

    __shared__ float As[2][8][132];
    __shared__ float Bs[2][8][132];

    const int b   = blockIdx.z;
    const int t0  = blockIdx.x * 128;
    const int n0  = blockIdx.y * 128;
    const int tid = threadIdx.x;

    const float* Ab = A + (size_t)b * T * LDA;
    const float* Bb = Bm + (size_t)b * 513 * 256;

    const int am  = tid >> 1;
    const int ak4 = (tid & 1) * 4;
    const int bk  = tid >> 5;
    const int bn  = (tid & 31) * 4;
    const int nb2 = tid >> 1;
    const int bk4 = (tid & 1) * 4;

    auto loadA = [&](int k0, int buf) {
        float4 v = make_float4(0.f, 0.f, 0.f, 0.f);
        int t = t0 + am;
        if (t < T)
            v = *reinterpret_cast<const float4*>(Ab + (size_t)t * LDA + k0 + ak4);
        As[buf][ak4 + 0][am] = v.x;
        As[buf][ak4 + 1][am] = v.y;
        As[buf][ak4 + 2][am] = v.z;
        As[buf][ak4 + 3][am] = v.w;
    };

    auto loadB = [&](int k0, int buf) {
        if (MODE == 2) {
            float4 v = make_float4(0.f, 0.f, 0.f, 0.f);
            int s = n0 + nb2;
            if (s < 513)
                v = *reinterpret_cast<const float4*>(Bb + (size_t)s * 256 + k0 + bk4);
            Bs[buf][bk4 + 0][nb2] = v.x;
            Bs[buf][bk4 + 1][nb2] = v.y;
            Bs[buf][bk4 + 2][nb2] = v.z;
            Bs[buf][bk4 + 3][nb2] = v.w;
        } else {
            float4 v = make_float4(0.f, 0.f, 0.f, 0.f);
            int kr = k0 + bk;
            if (kr < 513)
                v = *reinterpret_cast<const float4*>(Bb + (size_t)kr * 256 + n0 + bn);
            *reinterpret_cast<float4*>(&Bs[buf][bk][bn]) = v;
        }
    };

    const int tx = tid & 15;
    const int ty = tid >> 4;

    float acc[8][8];
#pragma unroll
    for (int i = 0; i < 8; i++)
#pragma unroll
        for (int j = 0; j < 8; j++) acc[i][j] = 0.f;

    loadA(0, 0);
    loadB(0, 0);
    __syncthreads();

    for (int s = 0; s < NSTEP; ++s) {
        int buf = s & 1;
        if (s + 1 < NSTEP) {
            loadA((s + 1) * 8, buf ^ 1);
            loadB((s + 1) * 8, buf ^ 1);
        }
#pragma unroll
        for (int k = 0; k < 8; ++k) {
            float4 a0 = *reinterpret_cast<const float4*>(&As[buf][k][ty * 4]);
            float4 a1 = *reinterpret_cast<const float4*>(&As[buf][k][64 + ty * 4]);
            float4 b0 = *reinterpret_cast<const float4*>(&Bs[buf][k][tx * 4]);
            float4 b1 = *reinterpret_cast<const float4*>(&Bs[buf][k][64 + tx * 4]);
            float av[8] = {a0.x, a0.y, a0.z, a0.w, a1.x, a1.y, a1.z, a1.w};
            float bv[8] = {b0.x, b0.y, b0.z, b0.w, b1.x, b1.y, b1.z, b1.w};
#pragma unroll
            for (int i = 0; i < 8; i++)
#pragma unroll
                for (int j = 0; j < 8; j++)
                    acc[i][j] = fmaf(av[i], bv[j], acc[i][j]);
        }
        __syncthreads();
    }

#pragma unroll
    for (int i = 0; i < 8; i++) {
        int m = (i < 4) ? (ty * 4 + i) : (64 + ty * 4 + (i - 4));
        int t = t0 + m;
        if (t >= T) continue;
        if (MODE == 2) {
            float* crow = Cg + ((size_t)b * T + t) * SPAD;
            int lim2 = lens[b] + lenoff;
#pragma unroll
            for (int j = 0; j < 8; j++) {
                int s_ = n0 + ((j < 4) ? (tx * 4 + j) : (64 + tx * 4 + (j - 4)));
                if (s_ < 513) {
                    float vv = 2.f * acc[i][j] - extra[(size_t)b * TPH + s_];
                    if (s_ >= lim2) vv = -1e9f;
                    crow[s_] = vv;
                }
            }
        } else {
            float* crow = Cg + ((size_t)b * T + t) * 512 + 256;
#pragma unroll
            for (int jh = 0; jh < 2; jh++) {
                int c = jh * 64 + tx * 4;
                float4 o;
                o.x = acc[i][jh * 4 + 0];
                o.y = acc[i][jh * 4 + 1];
                o.z = acc[i][jh * 4 + 2];
                o.w = acc[i][jh * 4 + 3];
                *reinterpret_cast<float4*>(crow + n0 + c) = o;
            }
        }
    }
}

// ---------------------------------------------------------------------------
// ||ph_enc||^2 per row
// ---------------------------------------------------------------------------
__global__ void phsq_kernel(const float* __restrict__ ep, float* __restrict__ sq) {
    int row = blockIdx.x;
    int lane = threadIdx.x;
    const float* r = ep + (size_t)row * 256;
    float s = 0.f;
#pragma unroll
    for (int j = 0; j < 2; j++) {
        float4 v = *reinterpret_cast<const float4*>(r + lane * 4 + j * 128);
        s += v.x * v.x + v.y * v.y + v.z * v.z + v.w * v.w;
    }
#pragma unroll
    for (int o = 16; o; o >>= 1) s += __shfl_xor_sync(0xffffffffu, s, o);
    if (lane == 0) sq[row] = s;
}

// ---------------------------------------------------------------------------
// Row softmax over 513 logits (stride SPAD), zero pad columns
// ---------------------------------------------------------------------------
__global__ void softmax_kernel(float* __restrict__ dots) {
    size_t row = blockIdx.x;
    float* p = dots + row * SPAD;
    int tid = threadIdx.x;
    int lane = tid & 31, wid = tid >> 5;
    __shared__ float red[32];

    float v[5];
    float mx = -3.0e38f;
#pragma unroll
    for (int j = 0; j < 5; j++) {
        int idx = tid + j * 128;
        v[j] = (idx < 513) ? p[idx] : -3.0e38f;
        mx = fmaxf(mx, v[j]);
    }
#pragma unroll
    for (int o = 16; o; o >>= 1) mx = fmaxf(mx, __shfl_xor_sync(0xffffffffu, mx, o));
    if (lane == 0) red[wid] = mx;
    __syncthreads();
    if (tid < 32) {
        float m = (tid < 4) ? red[tid] : -3.0e38f;
#pragma unroll
        for (int o = 2; o; o >>= 1) m = fmaxf(m, __shfl_xor_sync(0xffffffffu, m, o));
        if (tid == 0) red[0] = m;
    }
    __syncthreads();
    mx = red[0];
    __syncthreads();

    float s = 0.f;
#pragma unroll
    for (int j = 0; j < 5; j++) {
        int idx = tid + j * 128;
        if (idx < 513) { v[j] = expf(v[j] - mx); s += v[j]; }
    }
#pragma unroll
    for (int o = 16; o; o >>= 1) s += __shfl_xor_sync(0xffffffffu, s, o);
    if (lane == 0) red[wid] = s;
    __syncthreads();
    if (tid < 32) {
        float t2 = (tid < 4) ? red[tid] : 0.f;
#pragma unroll
        for (int o = 2; o; o >>= 1) t2 += __shfl_xor_sync(0xffffffffu, t2, o);
        if (tid == 0) red[0] = t2;
    }
    __syncthreads();
    float inv = 1.f / red[0];
#pragma unroll
    for (int j = 0; j < 5; j++) {
        int idx = tid + j * 128;
        if (idx < 513) p[idx] = v[j] * inv;
    }
    if (tid < SPAD - 513) p[513 + tid] = 0.f;
}

// ---------------------------------------------------------------------------
// Launcher
// ---------------------------------------------------------------------------
extern "C" void kernel_launch(void* const* d_in, const int* in_sizes, int n_in,
                              void* d_out, int out_size)
{
    const float* mels = (const float*)d_in[0];
    const int*   phon = (const int*)  d_in[1];
    const int*   mlen = (const int*)  d_in[2];
    const int*   plen = (const int*)  d_in[3];
    const float* emb  = (const float*)d_in[4];
    const float* mcw  = (const float*)d_in[5];
    const float* mcb  = (const float*)d_in[6];
    const float* phw  = (const float*)d_in[7];
    const float* phb  = (const float*)d_in[8];
    const float* melw = (const float*)d_in[9];
    const float* melb = (const float*)d_in[10];
    float* out = (float*)d_out;

    float *bufA, *bufB, *ph0, *ph1, *dots, *phsq;
    __half *hw, *hwf, *hmels, *hA, *hB, *hp0, *hp1;
    cudaGetSymbolAddress((void**)&bufA, g_bufA);
    cudaGetSymbolAddress((void**)&bufB, g_bufB);
    cudaGetSymbolAddress((void**)&ph0,  g_ph0);
    cudaGetSymbolAddress((void**)&ph1,  g_ph1);
    cudaGetSymbolAddress((void**)&dots, g_dots);
    cudaGetSymbolAddress((void**)&phsq, g_phsq);
    cudaGetSymbolAddress((void**)&hw,   g_hw);
    cudaGetSymbolAddress((void**)&hwf,  g_hwf);
    cudaGetSymbolAddress((void**)&hmels,g_hmels);
    cudaGetSymbolAddress((void**)&hA,   g_hA);
    cudaGetSymbolAddress((void**)&hB,   g_hB);
    cudaGetSymbolAddress((void**)&hp0,  g_hp0);
    cudaGetSymbolAddress((void**)&hp1,  g_hp1);

    // SMEM: 3 stages x (128+128)*40 halves = 61440 bytes
    const int SMEMSZ = 3 * 2 * 128 * LDH * 2;
    cudaFuncSetAttribute(conv_mma<0>, cudaFuncAttributeMaxDynamicSharedMemorySize, SMEMSZ);
    cudaFuncSetAttribute(conv_mma<1>, cudaFuncAttributeMaxDynamicSharedMemorySize, SMEMSZ);

    // 1. pack weights (ph -> slots 0..3, mel -> slots 4..7); mels -> fp16
    pack_glu_w<<<(4 * 512 * 768 + 255) / 256, 256>>>(phw, hw);
    pack_glu_w<<<(4 * 512 * 768 + 255) / 256, 256>>>(melw, hw + (size_t)4 * 512 * 768);
    pack_front_w<<<(256 * 256 + 255) / 256, 256>>>(mcw, hwf);
    f2h_kernel<<<(NB * TMEL * 80 / 4 + 255) / 256, 256>>>(mels, hmels, NB * TMEL * 80 / 4);

    // 2. phoneme embedding (fp32 + fp16 shadow)
    embed_kernel<<<NB * TPH, 64>>>(phon, emb, ph0, hp0);

    // 3. mel front conv -> bufA (+hA shadow)
    {
        dim3 g((TMEL + 127) / 128, 2, NB);
        conv_mma<1><<<g, 256, SMEMSZ>>>(hmels, nullptr, hwf, mcb, bufA, hA,
                                        nullptr, 0, TMEL, 256);
    }

    // 4. phoneme GLU blocks (valid s <= len => lim = len + 1)
    {
        float* pin = ph0;  float* pout = ph1;
        __half* hin = hp0; __half* hpo = hp1;
        dim3 g((TPH + 127) / 128, 4, NB);
        for (int i = 0; i < 4; i++) {
            conv_mma<0><<<g, 256, SMEMSZ>>>(hin, pin, hw + (size_t)i * 512 * 768,
                                            phb + i * 512, pout, hpo, plen, 1, TPH, 256);
            float* t1 = pin; pin = pout; pout = t1;
            __half* t2 = hin; hin = hpo; hpo = t2;
        }
        // final ph encoding in ph0 (fp32)
    }

    // 5. mel GLU blocks (valid t < len => lim = len)
    {
        float* pin = bufA;  float* pout = bufB;
        __half* hin = hA;   __half* hpo = hB;
        dim3 g((TMEL + 127) / 128, 4, NB);
        for (int i = 0; i < 4; i++) {
            if (i < 3) {
                conv_mma<0><<<g, 256, SMEMSZ>>>(hin, pin, hw + (size_t)(4 + i) * 512 * 768,
                                                melb + i * 512, pout, hpo, mlen, 0, TMEL, 256);
                float* t1 = pin; pin = pout; pout = t1;
                __half* t2 = hin; hin = hpo; hpo = t2;
            } else {
                // final block writes mel_enc directly into out[:, :, 0:256]
                conv_mma<0><<<g, 256, SMEMSZ>>>(hin, pin, hw + (size_t)(4 + i) * 512 * 768,
                                                melb + i * 512, out, hpo, mlen, 0, TMEL, 512);
            }
        }
    }

    // 6. phoneme squared norms
    phsq_kernel<<<NB * TPH, 32>>>(ph0, phsq);

    // 7. dots (fp32): logits = 2*dot - ph_sq, masked
    {
        dim3 g((TMEL + 127) / 128, (TPH + 127) / 128, NB);
        gemm128<2><<<g, 256>>>(out, ph0, phsq, dots, plen, 1, TMEL);
    }

    // 8. softmax over phoneme axis
    softmax_kernel<<<NB * TMEL, 128>>>(dots);

    // 9. context (fp32) -> out[:, :, 256:512]
    {
        dim3 g((TMEL + 127) / 128, 2, NB);
        gemm128<3><<<g, 256>>>(dots, ph0, nullptr, out, nullptr, 0, TMEL);
    }
}

// round 13
// speedup vs baseline: 4.0418x; 1.4178x over previous
#include <cuda_runtime.h>
#include <cuda_fp16.h>
#include <cuda_bf16.h>
#include <math.h>
#include <stdint.h>

// Problem constants (fixed by dataset)
#define NB   32
#define TMEL 2000
#define TPH  513
#define DIM  256
#define SPAD 520
#define KPAD 544    // padded phoneme axis for fp16 probs / phT (multiple of 32)

// fp32 buffers
static __device__ float g_bufA [NB * TMEL * DIM];
static __device__ float g_bufB [NB * TMEL * DIM];
static __device__ float g_ph0  [NB * TPH * DIM];
static __device__ float g_ph1  [NB * TPH * DIM];
static __device__ float g_dots [NB * TMEL * SPAD];
static __device__ float g_phsq [NB * TPH];
// fp16 weights + activation shadows
static __device__ __half g_hw   [8 * 512 * 768];
static __device__ __half g_hwf  [256 * 256];
static __device__ __half g_hmels[NB * TMEL * 80];
static __device__ __half g_hA   [NB * TMEL * DIM];
static __device__ __half g_hB   [NB * TMEL * DIM];
static __device__ __half g_hp0  [NB * TPH * DIM];
static __device__ __half g_hp1  [NB * TPH * DIM];
// fp16 attention operands
static __device__ __half g_probs[NB * TMEL * KPAD];   // softmax output, pads zeroed
static __device__ __half g_phT  [NB * DIM * KPAD];    // ph_enc transposed [b][d][s]

// ---------------------------------------------------------------------------
// Helpers
// ---------------------------------------------------------------------------
__device__ __forceinline__ uint32_t smem_u32(const void* p) {
    uint32_t a;
    asm("{ .reg .u64 t; cvta.to.shared.u64 t, %1; cvt.u32.u64 %0, t; }" : "=r"(a) : "l"(p));
    return a;
}
__device__ __forceinline__ void cp16(uint32_t dst, const void* src, uint32_t nbytes) {
    asm volatile("cp.async.ca.shared.global [%0], [%1], 16, %2;"
                 :: "r"(dst), "l"(src), "r"(nbytes) : "memory");
}
#define CP_COMMIT() asm volatile("cp.async.commit_group;" ::: "memory")
#define CP_WAIT1()  asm volatile("cp.async.wait_group 1;" ::: "memory")
#define CP_WAIT0()  asm volatile("cp.async.wait_group 0;" ::: "memory")

// mma.sync m16n8k16 fp16 inputs, fp32 accumulate
__device__ __forceinline__ void mma_f16(float* c, const uint32_t* a, uint32_t b0, uint32_t b1) {
    asm volatile(
        "mma.sync.aligned.m16n8k16.row.col.f32.f16.f16.f32 "
        "{%0,%1,%2,%3}, {%4,%5,%6,%7}, {%8,%9}, {%0,%1,%2,%3};"
        : "+f"(c[0]), "+f"(c[1]), "+f"(c[2]), "+f"(c[3])
        : "r"(a[0]), "r"(a[1]), "r"(a[2]), "r"(a[3]), "r"(b0), "r"(b1));
}

// ---------------------------------------------------------------------------
// Weight packing
// ---------------------------------------------------------------------------
__global__ void pack_glu_w(const float* __restrict__ w, __half* __restrict__ wp) {
    int i = blockIdx.x * blockDim.x + threadIdx.x;
    if (i >= 4 * 512 * 768) return;
    int kk = i % 768;
    int r = i / 768;
    int o = r & 511;
    int blk = r >> 9;
    int tap = kk >> 8;
    int ci = kk & 255;
    wp[i] = __float2half_rn(w[(((size_t)blk * 512 + o) * 256 + ci) * 3 + tap]);
}

__global__ void pack_front_w(const float* __restrict__ w, __half* __restrict__ wp) {
    int i = blockIdx.x * blockDim.x + threadIdx.x;
    if (i >= 256 * 256) return;
    int kk = i & 255;
    int o = i >> 8;
    float v = 0.f;
    if (kk < 240) {
        int tap = kk / 80;
        int ci = kk - tap * 80;
        v = w[((size_t)o * 80 + ci) * 3 + tap];
    }
    wp[i] = __float2half_rn(v);
}

__global__ void f2h_kernel(const float* __restrict__ in, __half* __restrict__ out, int n4) {
    int i = blockIdx.x * blockDim.x + threadIdx.x;
    if (i >= n4) return;
    float4 v = *reinterpret_cast<const float4*>(in + i * 4);
    *reinterpret_cast<__half2*>(out + i * 4)     = __floats2half2_rn(v.x, v.y);
    *reinterpret_cast<__half2*>(out + i * 4 + 2) = __floats2half2_rn(v.z, v.w);
}

// ---------------------------------------------------------------------------
// Phoneme embedding (prepended blank 0) -> fp32 + fp16 shadow
// ---------------------------------------------------------------------------
__global__ void embed_kernel(const int* __restrict__ ph, const float* __restrict__ emb,
                             float* __restrict__ out, __half* __restrict__ hout) {
    int row = blockIdx.x;
    int b = row / TPH;
    int s = row - b * TPH;
    int tok = (s == 0) ? 0 : ph[b * 512 + (s - 1)];
    float4 v = *reinterpret_cast<const float4*>(emb + (size_t)tok * 256 + threadIdx.x * 4);
    *reinterpret_cast<float4*>(out + (size_t)row * 256 + threadIdx.x * 4) = v;
    *reinterpret_cast<__half2*>(hout + (size_t)row * 256 + threadIdx.x * 4)     = __floats2half2_rn(v.x, v.y);
    *reinterpret_cast<__half2*>(hout + (size_t)row * 256 + threadIdx.x * 4 + 2) = __floats2half2_rn(v.z, v.w);
}

// ---------------------------------------------------------------------------
// ph_enc fp16 transpose: hp0 [b][s][d] -> phT [b][d][s] (s padded to KPAD, zeros)
// ---------------------------------------------------------------------------
__global__ void transpose_ph(const __half* __restrict__ hp, __half* __restrict__ phT) {
    int bd = blockIdx.x;
    int b = bd >> 8;
    int d = bd & 255;
    int s = threadIdx.x * 2;
    __half z = __float2half(0.f);
    __half v0 = (s     < TPH) ? hp[((size_t)b * TPH + s) * 256 + d]     : z;
    __half v1 = (s + 1 < TPH) ? hp[((size_t)b * TPH + s + 1) * 256 + d] : z;
    *reinterpret_cast<__half2*>(phT + ((size_t)b * 256 + d) * KPAD + s) = __halves2half2(v0, v1);
}

// ---------------------------------------------------------------------------
// fp16 mma.sync conv GEMM with fused GLU epilogue, 3-stage cp.async ring.
// (unchanged from R11 — proven)
// ---------------------------------------------------------------------------
#define LDH 40
template <int MODE>
__launch_bounds__(256, 2)
__global__ void conv_mma(const __half* __restrict__ Ah, const float* __restrict__ Af,
                         const __half* __restrict__ Bw, const float* __restrict__ bias,
                         float* __restrict__ out, __half* __restrict__ hout,
                         const int* __restrict__ lens, int lenoff, int T, int ldout)
{
    constexpr int CI = (MODE == 0) ? 256 : 80;
    constexpr int K  = (MODE == 0) ? 768 : 256;
    constexpr int NS = K / 32;
    constexpr int STAGE = 2 * 128 * LDH;
    constexpr int BOFF  = 128 * LDH;

    extern __shared__ __half smh[];

    const int tid = threadIdx.x;
    const int b   = blockIdx.z;
    const int t0  = blockIdx.x * 128;
    const int n0  = blockIdx.y * 64;

    const __half* Ahb = Ah + (size_t)b * T * CI;
    const float*  Afb = Af + (size_t)b * T * 256;
    const int lim = (MODE == 0) ? (lens[b] + lenoff) : 0x7fffffff;

    const int lrow = tid >> 1;
    const int lhc  = (tid & 1) * 16;
    const int slab = lrow >> 6;
    const int nloc = lrow & 63;
    const int wrow = (MODE == 0) ? (n0 + slab * 256 + nloc) : (n0 + slab * 128 + nloc);
    const __half* Brow = Bw + (size_t)wrow * K;

    const uint32_t smb = smem_u32(smh);

    auto loadStage = [&](int s) {
        const int st = s % 3;
        const int k0 = s * 32;
        uint32_t adst = smb + (st * STAGE + lrow * LDH + lhc) * 2;
#pragma unroll
        for (int j = 0; j < 2; j++) {
            int kk = k0 + lhc + j * 8;
            int tap = kk / CI;
            int ci = kk - tap * CI;
            int t = t0 + lrow + tap - 1;
            bool ok = (t >= 0) && (t < T) && (t < lim);
            if (MODE == 1) ok = ok && (kk < 240);
            int tc = ok ? t : 0;
            cp16(adst + j * 16, Ahb + (size_t)tc * CI + ci, ok ? 16u : 0u);
        }
        uint32_t bdst = smb + (st * STAGE + BOFF + lrow * LDH + lhc) * 2;
        const __half* bsrc = Brow + k0 + lhc;
#pragma unroll
        for (int j = 0; j < 2; j++)
            cp16(bdst + j * 16, bsrc + j * 8, 16u);
        CP_COMMIT();
    };

    const int lane = tid & 31;
    const int g    = lane >> 2;
    const int tIg  = lane & 3;
    const int wm   = (tid >> 5) & 3;
    const int wn   = (tid >> 5) >> 2;

    float acc[2][2][4][4];
#pragma unroll
    for (int s1 = 0; s1 < 2; s1++)
#pragma unroll
        for (int mt = 0; mt < 2; mt++)
#pragma unroll
            for (int nt = 0; nt < 4; nt++)
#pragma unroll
                for (int q = 0; q < 4; q++) acc[s1][mt][nt][q] = 0.f;

    loadStage(0);
    loadStage(1);

    for (int s = 0; s < NS; ++s) {
        if (s + 1 < NS) { CP_WAIT1(); } else { CP_WAIT0(); }
        __syncthreads();
        if (s + 2 < NS) loadStage(s + 2);

        const int st = s % 3;
        const __half* As = smh + st * STAGE;
        const __half* Bs = smh + st * STAGE + BOFF;
#pragma unroll
        for (int ks = 0; ks < 2; ks++) {
            const int kb = ks * 16 + 2 * tIg;
            uint32_t af[2][4];
#pragma unroll
            for (int mt = 0; mt < 2; mt++) {
                const __half* ar = As + (wm * 32 + mt * 16 + g) * LDH;
                af[mt][0] = *reinterpret_cast<const uint32_t*>(ar + kb);
                af[mt][1] = *reinterpret_cast<const uint32_t*>(ar + 8 * LDH + kb);
                af[mt][2] = *reinterpret_cast<const uint32_t*>(ar + kb + 8);
                af[mt][3] = *reinterpret_cast<const uint32_t*>(ar + 8 * LDH + kb + 8);
            }
#pragma unroll
            for (int s1 = 0; s1 < 2; s1++) {
#pragma unroll
                for (int nt = 0; nt < 4; nt++) {
                    const __half* br = Bs + (s1 * 64 + wn * 32 + nt * 8 + g) * LDH;
                    uint32_t b0 = *reinterpret_cast<const uint32_t*>(br + kb);
                    uint32_t b1 = *reinterpret_cast<const uint32_t*>(br + kb + 8);
                    mma_f16(acc[s1][0][nt], af[0], b0, b1);
                    mma_f16(acc[s1][1][nt], af[1], b0, b1);
                }
            }
        }
    }

    const float SH = 0.70710678118654752440f;
#pragma unroll
    for (int mt = 0; mt < 2; mt++) {
#pragma unroll
        for (int h = 0; h < 2; h++) {
            const int t = t0 + wm * 32 + mt * 16 + g + 8 * h;
            if (t >= T) continue;
            if (MODE == 0) {
                const bool xon = (t < lim);
                const float* xr = Afb + (size_t)t * 256;
                float*  orow = out  + ((size_t)b * T + t) * ldout;
                __half* hrow = hout + ((size_t)b * T + t) * 256;
#pragma unroll
                for (int nt = 0; nt < 4; nt++) {
                    const int c = n0 + wn * 32 + nt * 8 + 2 * tIg;
                    float a0 = acc[0][mt][nt][2 * h + 0] + __ldg(bias + c + 0);
                    float a1 = acc[0][mt][nt][2 * h + 1] + __ldg(bias + c + 1);
                    float g0 = acc[1][mt][nt][2 * h + 0] + __ldg(bias + 256 + c + 0);
                    float g1 = acc[1][mt][nt][2 * h + 1] + __ldg(bias + 256 + c + 1);
                    float2 x = make_float2(0.f, 0.f);
                    if (xon) x = *reinterpret_cast<const float2*>(xr + c);
                    float2 o;
                    o.x = (a0 / (1.f + expf(-g0)) + x.x) * SH;
                    o.y = (a1 / (1.f + expf(-g1)) + x.y) * SH;
                    *reinterpret_cast<float2*>(orow + c) = o;
                    *reinterpret_cast<__half2*>(hrow + c) = __floats2half2_rn(o.x, o.y);
                }
            } else {
                float*  orow = out  + ((size_t)b * T + t) * ldout;
                __half* hrow = hout + ((size_t)b * T + t) * 256;
#pragma unroll
                for (int s1 = 0; s1 < 2; s1++) {
#pragma unroll
                    for (int nt = 0; nt < 4; nt++) {
                        const int c = n0 + s1 * 128 + wn * 32 + nt * 8 + 2 * tIg;
                        float2 o;
                        o.x = acc[s1][mt][nt][2 * h + 0] + __ldg(bias + c + 0);
                        o.y = acc[s1][mt][nt][2 * h + 1] + __ldg(bias + c + 1);
                        *reinterpret_cast<float2*>(orow + c) = o;
                        *reinterpret_cast<__half2*>(hrow + c) = __floats2half2_rn(o.x, o.y);
                    }
                }
            }
        }
    }
}

// ---------------------------------------------------------------------------
// fp16 attention GEMMs, same skeleton. 128 x 128 tile.
// EPI 0 (dots NT): A = hmel[b][t][256], B = hph[b][s][256] (s < 513 zero-padded)
//                  epilogue: logits = 2*acc - phsq[s]; mask s >= lim -> -1e9; fp32.
// EPI 1 (context): A = probs[b][t][KPAD], B = phT[b][d][KPAD]
//                  epilogue: out[b][t][256 + d] = acc.
// ---------------------------------------------------------------------------
template <int EPI>
__launch_bounds__(256, 2)
__global__ void attn_mma(const __half* __restrict__ Ah, const __half* __restrict__ Bh,
                         const float* __restrict__ phsq, float* __restrict__ outp,
                         const int* __restrict__ lens, int lenoff, int T)
{
    constexpr int K  = (EPI == 0) ? 256 : KPAD;
    constexpr int NS = K / 32;
    constexpr int LDA = (EPI == 0) ? 256 : KPAD;
    constexpr int LDB = (EPI == 0) ? 256 : KPAD;
    constexpr int STAGE = 2 * 128 * LDH;
    constexpr int BOFF  = 128 * LDH;

    extern __shared__ __half smh[];

    const int tid = threadIdx.x;
    const int b   = blockIdx.z;
    const int t0  = blockIdx.x * 128;
    const int n0  = blockIdx.y * 128;

    const __half* Ab = Ah + (size_t)b * T * LDA;
    const __half* Bb = Bh + (size_t)b * ((EPI == 0) ? TPH : 256) * LDB;

    const int lrow = tid >> 1;
    const int lhc  = (tid & 1) * 16;
    const uint32_t smb = smem_u32(smh);

    auto loadStage = [&](int s) {
        const int st = s % 3;
        const int k0 = s * 32;
        // A
        {
            int t = t0 + lrow;
            bool ok = (t < T);
            int tc = ok ? t : 0;
            uint32_t adst = smb + (st * STAGE + lrow * LDH + lhc) * 2;
            const __half* asrc = Ab + (size_t)tc * LDA + k0 + lhc;
#pragma unroll
            for (int j = 0; j < 2; j++)
                cp16(adst + j * 16, asrc + j * 8, ok ? 16u : 0u);
        }
        // B
        {
            int n = n0 + lrow;
            bool ok = (EPI == 1) || (n < TPH);
            int nc = ok ? n : 0;
            uint32_t bdst = smb + (st * STAGE + BOFF + lrow * LDH + lhc) * 2;
            const __half* bsrc = Bb + (size_t)nc * LDB + k0 + lhc;
#pragma unroll
            for (int j = 0; j < 2; j++)
                cp16(bdst + j * 16, bsrc + j * 8, ok ? 16u : 0u);
        }
        CP_COMMIT();
    };

    const int lane = tid & 31;
    const int g    = lane >> 2;
    const int tIg  = lane & 3;
    const int wm   = (tid >> 5) & 3;
    const int wn   = (tid >> 5) >> 2;

    float acc[2][2][4][4];
#pragma unroll
    for (int s1 = 0; s1 < 2; s1++)
#pragma unroll
        for (int mt = 0; mt < 2; mt++)
#pragma unroll
            for (int nt = 0; nt < 4; nt++)
#pragma unroll
                for (int q = 0; q < 4; q++) acc[s1][mt][nt][q] = 0.f;

    loadStage(0);
    loadStage(1);

    for (int s = 0; s < NS; ++s) {
        if (s + 1 < NS) { CP_WAIT1(); } else { CP_WAIT0(); }
        __syncthreads();
        if (s + 2 < NS) loadStage(s + 2);

        const int st = s % 3;
        const __half* As = smh + st * STAGE;
        const __half* Bs = smh + st * STAGE + BOFF;
#pragma unroll
        for (int ks = 0; ks < 2; ks++) {
            const int kb = ks * 16 + 2 * tIg;
            uint32_t af[2][4];
#pragma unroll
            for (int mt = 0; mt < 2; mt++) {
                const __half* ar = As + (wm * 32 + mt * 16 + g) * LDH;
                af[mt][0] = *reinterpret_cast<const uint32_t*>(ar + kb);
                af[mt][1] = *reinterpret_cast<const uint32_t*>(ar + 8 * LDH + kb);
                af[mt][2] = *reinterpret_cast<const uint32_t*>(ar + kb + 8);
                af[mt][3] = *reinterpret_cast<const uint32_t*>(ar + 8 * LDH + kb + 8);
            }
#pragma unroll
            for (int s1 = 0; s1 < 2; s1++) {
#pragma unroll
                for (int nt = 0; nt < 4; nt++) {
                    const __half* br = Bs + (s1 * 64 + wn * 32 + nt * 8 + g) * LDH;
                    uint32_t b0 = *reinterpret_cast<const uint32_t*>(br + kb);
                    uint32_t b1 = *reinterpret_cast<const uint32_t*>(br + kb + 8);
                    mma_f16(acc[s1][0][nt], af[0], b0, b1);
                    mma_f16(acc[s1][1][nt], af[1], b0, b1);
                }
            }
        }
    }

    const int lim = (EPI == 0) ? (lens[b] + lenoff) : 0;
#pragma unroll
    for (int mt = 0; mt < 2; mt++) {
#pragma unroll
        for (int h = 0; h < 2; h++) {
            const int t = t0 + wm * 32 + mt * 16 + g + 8 * h;
            if (t >= T) continue;
            if (EPI == 0) {
                float* crow = outp + ((size_t)b * T + t) * SPAD;
                const float* sqb = phsq + (size_t)b * TPH;
#pragma unroll
                for (int s1 = 0; s1 < 2; s1++) {
#pragma unroll
                    for (int nt = 0; nt < 4; nt++) {
#pragma unroll
                        for (int e = 0; e < 2; e++) {
                            const int s_ = n0 + s1 * 64 + wn * 32 + nt * 8 + 2 * tIg + e;
                            if (s_ < TPH) {
                                float vv = 2.f * acc[s1][mt][nt][2 * h + e] - sqb[s_];
                                if (s_ >= lim) vv = -1e9f;
                                crow[s_] = vv;
                            }
                        }
                    }
                }
            } else {
                float* crow = outp + ((size_t)b * T + t) * 512 + 256;
#pragma unroll
                for (int s1 = 0; s1 < 2; s1++) {
#pragma unroll
                    for (int nt = 0; nt < 4; nt++) {
                        const int c = n0 + s1 * 64 + wn * 32 + nt * 8 + 2 * tIg;
                        float2 o;
                        o.x = acc[s1][mt][nt][2 * h + 0];
                        o.y = acc[s1][mt][nt][2 * h + 1];
                        *reinterpret_cast<float2*>(crow + c) = o;
                    }
                }
            }
        }
    }
}

// ---------------------------------------------------------------------------
// ||ph_enc||^2 per row
// ---------------------------------------------------------------------------
__global__ void phsq_kernel(const float* __restrict__ ep, float* __restrict__ sq) {
    int row = blockIdx.x;
    int lane = threadIdx.x;
    const float* r = ep + (size_t)row * 256;
    float s = 0.f;
#pragma unroll
    for (int j = 0; j < 2; j++) {
        float4 v = *reinterpret_cast<const float4*>(r + lane * 4 + j * 128);
        s += v.x * v.x + v.y * v.y + v.z * v.z + v.w * v.w;
    }
#pragma unroll
    for (int o = 16; o; o >>= 1) s += __shfl_xor_sync(0xffffffffu, s, o);
    if (lane == 0) sq[row] = s;
}

// ---------------------------------------------------------------------------
// Row softmax over 513 fp32 logits (stride SPAD) -> fp16 probs (stride KPAD,
// pads zeroed)
// ---------------------------------------------------------------------------
__global__ void softmax_kernel(const float* __restrict__ dots, __half* __restrict__ probs) {
    size_t row = blockIdx.x;
    const float* p = dots + row * SPAD;
    __half* ph = probs + row * KPAD;
    int tid = threadIdx.x;
    int lane = tid & 31, wid = tid >> 5;
    __shared__ float red[32];

    float v[5];
    float mx = -3.0e38f;
#pragma unroll
    for (int j = 0; j < 5; j++) {
        int idx = tid + j * 128;
        v[j] = (idx < TPH) ? p[idx] : -3.0e38f;
        mx = fmaxf(mx, v[j]);
    }
#pragma unroll
    for (int o = 16; o; o >>= 1) mx = fmaxf(mx, __shfl_xor_sync(0xffffffffu, mx, o));
    if (lane == 0) red[wid] = mx;
    __syncthreads();
    if (tid < 32) {
        float m = (tid < 4) ? red[tid] : -3.0e38f;
#pragma unroll
        for (int o = 2; o; o >>= 1) m = fmaxf(m, __shfl_xor_sync(0xffffffffu, m, o));
        if (tid == 0) red[0] = m;
    }
    __syncthreads();
    mx = red[0];
    __syncthreads();

    float s = 0.f;
#pragma unroll
    for (int j = 0; j < 5; j++) {
        int idx = tid + j * 128;
        if (idx < TPH) { v[j] = expf(v[j] - mx); s += v[j]; }
    }
#pragma unroll
    for (int o = 16; o; o >>= 1) s += __shfl_xor_sync(0xffffffffu, s, o);
    if (lane == 0) red[wid] = s;
    __syncthreads();
    if (tid < 32) {
        float t2 = (tid < 4) ? red[tid] : 0.f;
#pragma unroll
        for (int o = 2; o; o >>= 1) t2 += __shfl_xor_sync(0xffffffffu, t2, o);
        if (tid == 0) red[0] = t2;
    }
    __syncthreads();
    float inv = 1.f / red[0];
#pragma unroll
    for (int j = 0; j < 5; j++) {
        int idx = tid + j * 128;
        if (idx < TPH) ph[idx] = __float2half_rn(v[j] * inv);
        else if (idx < KPAD) ph[idx] = __float2half(0.f);
    }
}

// ---------------------------------------------------------------------------
// Launcher
// ---------------------------------------------------------------------------
extern "C" void kernel_launch(void* const* d_in, const int* in_sizes, int n_in,
                              void* d_out, int out_size)
{
    const float* mels = (const float*)d_in[0];
    const int*   phon = (const int*)  d_in[1];
    const int*   mlen = (const int*)  d_in[2];
    const int*   plen = (const int*)  d_in[3];
    const float* emb  = (const float*)d_in[4];
    const float* mcw  = (const float*)d_in[5];
    const float* mcb  = (const float*)d_in[6];
    const float* phw  = (const float*)d_in[7];
    const float* phb  = (const float*)d_in[8];
    const float* melw = (const float*)d_in[9];
    const float* melb = (const float*)d_in[10];
    float* out = (float*)d_out;

    float *bufA, *bufB, *ph0, *ph1, *dots, *phsq;
    __half *hw, *hwf, *hmels, *hA, *hB, *hp0, *hp1, *probs, *phT;
    cudaGetSymbolAddress((void**)&bufA, g_bufA);
    cudaGetSymbolAddress((void**)&bufB, g_bufB);
    cudaGetSymbolAddress((void**)&ph0,  g_ph0);
    cudaGetSymbolAddress((void**)&ph1,  g_ph1);
    cudaGetSymbolAddress((void**)&dots, g_dots);
    cudaGetSymbolAddress((void**)&phsq, g_phsq);
    cudaGetSymbolAddress((void**)&hw,   g_hw);
    cudaGetSymbolAddress((void**)&hwf,  g_hwf);
    cudaGetSymbolAddress((void**)&hmels,g_hmels);
    cudaGetSymbolAddress((void**)&hA,   g_hA);
    cudaGetSymbolAddress((void**)&hB,   g_hB);
    cudaGetSymbolAddress((void**)&hp0,  g_hp0);
    cudaGetSymbolAddress((void**)&hp1,  g_hp1);
    cudaGetSymbolAddress((void**)&probs,g_probs);
    cudaGetSymbolAddress((void**)&phT,  g_phT);

    const int SMEMSZ = 3 * 2 * 128 * LDH * 2;   // 61440 B
    cudaFuncSetAttribute(conv_mma<0>, cudaFuncAttributeMaxDynamicSharedMemorySize, SMEMSZ);
    cudaFuncSetAttribute(conv_mma<1>, cudaFuncAttributeMaxDynamicSharedMemorySize, SMEMSZ);
    cudaFuncSetAttribute(attn_mma<0>, cudaFuncAttributeMaxDynamicSharedMemorySize, SMEMSZ);
    cudaFuncSetAttribute(attn_mma<1>, cudaFuncAttributeMaxDynamicSharedMemorySize, SMEMSZ);

    // 1. pack weights; mels -> fp16
    pack_glu_w<<<(4 * 512 * 768 + 255) / 256, 256>>>(phw, hw);
    pack_glu_w<<<(4 * 512 * 768 + 255) / 256, 256>>>(melw, hw + (size_t)4 * 512 * 768);
    pack_front_w<<<(256 * 256 + 255) / 256, 256>>>(mcw, hwf);
    f2h_kernel<<<(NB * TMEL * 80 / 4 + 255) / 256, 256>>>(mels, hmels, NB * TMEL * 80 / 4);

    // 2. phoneme embedding
    embed_kernel<<<NB * TPH, 64>>>(phon, emb, ph0, hp0);

    // 3. mel front conv -> bufA (+hA)
    {
        dim3 g((TMEL + 127) / 128, 2, NB);
        conv_mma<1><<<g, 256, SMEMSZ>>>(hmels, nullptr, hwf, mcb, bufA, hA,
                                        nullptr, 0, TMEL, 256);
    }

    // 4. phoneme GLU blocks (lim = len + 1)
    {
        float* pin = ph0;  float* pout = ph1;
        __half* hin = hp0; __half* hpo = hp1;
        dim3 g((TPH + 127) / 128, 4, NB);
        for (int i = 0; i < 4; i++) {
            conv_mma<0><<<g, 256, SMEMSZ>>>(hin, pin, hw + (size_t)i * 512 * 768,
                                            phb + i * 512, pout, hpo, plen, 1, TPH, 256);
            float* t1 = pin; pin = pout; pout = t1;
            __half* t2 = hin; hin = hpo; hpo = t2;
        }
        // final ph: fp32 in ph0, fp16 in hp0
    }

    // 5. mel GLU blocks (lim = len)
    {
        float* pin = bufA;  float* pout = bufB;
        __half* hin = hA;   __half* hpo = hB;
        dim3 g((TMEL + 127) / 128, 4, NB);
        for (int i = 0; i < 4; i++) {
            if (i < 3) {
                conv_mma<0><<<g, 256, SMEMSZ>>>(hin, pin, hw + (size_t)(4 + i) * 512 * 768,
                                                melb + i * 512, pout, hpo, mlen, 0, TMEL, 256);
                float* t1 = pin; pin = pout; pout = t1;
                __half* t2 = hin; hin = hpo; hpo = t2;
            } else {
                conv_mma<0><<<g, 256, SMEMSZ>>>(hin, pin, hw + (size_t)(4 + i) * 512 * 768,
                                                melb + i * 512, out, hpo, mlen, 0, TMEL, 512);
                // final mel: fp32 in out[:,:,0:256], fp16 shadow in hA
            }
        }
    }

    // 6. phoneme squared norms (fp32) + fp16 transpose of ph_enc
    phsq_kernel<<<NB * TPH, 32>>>(ph0, phsq);
    transpose_ph<<<NB * 256, KPAD / 2>>>(hp0, phT);

    // 7. dots (fp16 tensor): logits = 2*dot - ph_sq, masked -> fp32
    {
        dim3 g((TMEL + 127) / 128, (TPH + 127) / 128, NB);
        attn_mma<0><<<g, 256, SMEMSZ>>>(hA, hp0, phsq, dots, plen, 1, TMEL);
    }

    // 8. softmax -> fp16 probs (pads zeroed)
    softmax_kernel<<<NB * TMEL, 128>>>(dots, probs);

    // 9. context (fp16 tensor) -> out[:, :, 256:512]
    {
        dim3 g((TMEL + 127) / 128, 2, NB);
        attn_mma<1><<<g, 256, SMEMSZ>>>(probs, phT, nullptr, out, nullptr, 0, TMEL);
    }
}